// round 5
// baseline (speedup 1.0000x reference)
#include <cuda_runtime.h>
#include <cuda_bf16.h>
#include <cuda_fp16.h>
#include <math.h>
#include <stdint.h>

#define Bn 4
#define Sn 4096
#define Cn 256
#define En 256

typedef unsigned int u32;
typedef unsigned long long u64;

// quantization scale for Q/K 15-bit fixed point
#define QSCALE 4608.0f
#define FOLD_C1 (16384.0f / (QSCALE * QSCALE))
#define FOLD_C2 (128.0f   / (QSCALE * QSCALE))

// ------------------------------------------------------------------
// Static device scratch (no allocation allowed)
// ------------------------------------------------------------------
__device__ float g_V[Bn * Sn * En];
__device__ __align__(16) char g_Q8h[Bn * Sn * Cn];
__device__ __align__(16) char g_Q8l[Bn * Sn * Cn];
__device__ __align__(16) char g_K8h[Bn * Sn * Cn];
__device__ __align__(16) char g_K8l[Bn * Sn * Cn];
__device__ __half g_Vt[Bn * En * Sn];                 // V transposed fp16: [b][e][s]
__device__ float g_S[(size_t)Bn * Sn * Sn];           // 256 MB scores
__device__ __half g_P[(size_t)Bn * Sn * Sn];          // 128 MB normalized probs

// ------------------------------------------------------------------
// helpers
// ------------------------------------------------------------------
__device__ __forceinline__ u32 smem_u32(const void* p) {
    u32 a;
    asm("{ .reg .u64 t; cvta.to.shared.u64 t, %1; cvt.u32.u64 %0, t; }"
        : "=r"(a) : "l"(p));
    return a;
}
#define SW128(o) ((o) ^ (((o) >> 3) & 0x70))

__device__ __forceinline__ void cp16(u32 dst, const void* src) {
    asm volatile("cp.async.cg.shared.global [%0], [%1], 16;" :: "r"(dst), "l"(src));
}
#define CP_COMMIT() asm volatile("cp.async.commit_group;" ::: "memory")

#define LDSM_X4(r0, r1, r2, r3, addr)                                        \
    asm volatile("ldmatrix.sync.aligned.m8n8.x4.shared.b16 {%0,%1,%2,%3}, [%4];" \
                 : "=r"(r0), "=r"(r1), "=r"(r2), "=r"(r3) : "r"(addr))

#define MMA_F16(d, a, b0, b1)                                                \
    asm volatile("mma.sync.aligned.m16n8k16.row.col.f32.f16.f16.f32 "        \
                 "{%0,%1,%2,%3}, {%4,%5,%6,%7}, {%8,%9}, {%0,%1,%2,%3};"     \
                 : "+f"((d)[0]), "+f"((d)[1]), "+f"((d)[2]), "+f"((d)[3])    \
                 : "r"((a)[0]), "r"((a)[1]), "r"((a)[2]), "r"((a)[3]),       \
                   "r"(b0), "r"(b1))

#define MMA_S8(d, a, b0, b1)                                                 \
    asm volatile("mma.sync.aligned.m16n8k32.row.col.s32.s8.s8.s32 "          \
                 "{%0,%1,%2,%3}, {%4,%5,%6,%7}, {%8,%9}, {%0,%1,%2,%3};"     \
                 : "+r"((d)[0]), "+r"((d)[1]), "+r"((d)[2]), "+r"((d)[3])    \
                 : "r"((a)[0]), "r"((a)[1]), "r"((a)[2]), "r"((a)[3]),       \
                   "r"(b0), "r"(b1))

// f32x2 helpers for the FFMA QKV kernel
__device__ __forceinline__ u64 pk2(float lo, float hi) {
    u64 r; asm("mov.b64 %0, {%1,%2};" : "=l"(r) : "f"(lo), "f"(hi)); return r;
}
__device__ __forceinline__ void fma2(u64& d, u64 a, u64 b) {
    asm("fma.rn.f32x2 %0, %1, %2, %0;" : "+l"(d) : "l"(a), "l"(b));
}
__device__ __forceinline__ void upk2(u64 v, float& lo, float& hi) {
    asm("mov.b64 {%0,%1}, %2;" : "=f"(lo), "=f"(hi) : "l"(v));
}

// ==================================================================
// Kernel 1: QKV projections (FFMA). Q/K quantized to int8 hi/lo
// (15-bit fixed point), V written fp32.
// ==================================================================
__global__ __launch_bounds__(256)
void qkv_proj_kernel(const float* __restrict__ x,
                     const float* __restrict__ Wq, const float* __restrict__ bq,
                     const float* __restrict__ Wk, const float* __restrict__ bk,
                     const float* __restrict__ Wv, const float* __restrict__ bv)
{
    __shared__ float Xs[16][132];
    __shared__ float Wsh[16][64];

    int t  = threadIdx.x;
    int m0 = blockIdx.x * 128;
    int nb = blockIdx.y;
    int which = nb >> 2;
    int n0 = (nb & 3) * 64;

    const float* W; const float* bias;
    if (which == 0)      { W = Wq; bias = bq; }
    else if (which == 1) { W = Wk; bias = bk; }
    else                 { W = Wv; bias = bv; }

    int tr = t >> 4, tc = t & 15;

    u64 acc[8][2];
    #pragma unroll
    for (int i = 0; i < 8; i++) { acc[i][0] = 0ull; acc[i][1] = 0ull; }

    for (int kc = 0; kc < Cn; kc += 16) {
        __syncthreads();
        for (int i = t; i < 512; i += 256) {
            int row = i >> 2, seg = i & 3;
            float4 v = *(const float4*)&x[(size_t)(m0 + row) * Cn + kc + seg * 4];
            Xs[seg*4+0][row] = v.x; Xs[seg*4+1][row] = v.y;
            Xs[seg*4+2][row] = v.z; Xs[seg*4+3][row] = v.w;
        }
        {
            int row = t >> 4, seg = t & 15;
            *(float4*)&Wsh[row][seg*4] =
                *(const float4*)&W[(size_t)(kc + row) * 256 + n0 + seg * 4];
        }
        __syncthreads();

        #pragma unroll
        for (int k = 0; k < 16; ++k) {
            float4 a0 = *(float4*)&Xs[k][tr*8];
            float4 a1 = *(float4*)&Xs[k][tr*8 + 4];
            float4 bb = *(float4*)&Wsh[k][tc*4];
            u64 b01 = pk2(bb.x, bb.y), b23 = pk2(bb.z, bb.w);
            float av[8] = {a0.x,a0.y,a0.z,a0.w,a1.x,a1.y,a1.z,a1.w};
            #pragma unroll
            for (int i = 0; i < 8; ++i) {
                u64 ad = pk2(av[i], av[i]);
                fma2(acc[i][0], ad, b01);
                fma2(acc[i][1], ad, b23);
            }
        }
    }

    float4 bb4 = *(const float4*)&bias[n0 + tc*4];
    #pragma unroll
    for (int i = 0; i < 8; ++i) {
        float v[4];
        upk2(acc[i][0], v[0], v[1]);
        upk2(acc[i][1], v[2], v[3]);
        v[0] += bb4.x; v[1] += bb4.y; v[2] += bb4.z; v[3] += bb4.w;
        size_t idx = (size_t)(m0 + tr*8 + i) * 256 + n0 + tc*4;
        if (which == 2) {
            float4 r; r.x = v[0]; r.y = v[1]; r.z = v[2]; r.w = v[3];
            *(float4*)&g_V[idx] = r;
        } else {
            u32 ph = 0, pl = 0;
            #pragma unroll
            for (int j = 0; j < 4; ++j) {
                float qv = v[j] * QSCALE;
                qv = fminf(fmaxf(qv, -16320.0f), 16319.0f);
                int q15 = __float2int_rn(qv);
                int qh = (q15 + 64) >> 7;
                int ql = q15 - (qh << 7);
                ph |= ((u32)(unsigned char)(char)qh) << (j * 8);
                pl |= ((u32)(unsigned char)(char)ql) << (j * 8);
            }
            if (which == 0) {
                *(u32*)&g_Q8h[idx] = ph;
                *(u32*)&g_Q8l[idx] = pl;
            } else {
                *(u32*)&g_K8h[idx] = ph;
                *(u32*)&g_K8l[idx] = pl;
            }
        }
    }
}

// ==================================================================
// Kernel 2: transpose + convert V -> Vt[b][e][s] fp16
// ==================================================================
__global__ __launch_bounds__(256)
void conv_v_kernel()
{
    __shared__ float tile[32][33];
    int b  = blockIdx.z;
    int s0 = blockIdx.x * 32, e0 = blockIdx.y * 32;
    int tx = threadIdx.x, ty = threadIdx.y;

    #pragma unroll
    for (int j = ty; j < 32; j += 8)
        tile[j][tx] = g_V[((size_t)(b * Sn + s0 + j)) * En + e0 + tx];
    __syncthreads();
    #pragma unroll
    for (int j = ty; j < 32; j += 8) {
        float v = tile[tx][j];   // = V[s0+tx][e0+j]
        size_t o = ((size_t)(b * En + e0 + j)) * Sn + s0 + tx;
        g_Vt[o] = __float2half_rn(v);
    }
}

// ==================================================================
// Kernel 3: scores S[b] = Q[b] @ K[b]^T via int8 IMMA (15-bit split).
// Block tile 128(M) x 128(N), K=256 in two double-buffered 128-chunks.
// Warps: 2M x 4N, warp tile 64x32. Two s32 accums: hh, mx.
// ==================================================================
#define S8_AH 0
#define S8_AL (16*1024)
#define S8_BH (32*1024)
#define S8_BL (48*1024)
#define S8_CHUNK (64*1024)
#define SMEM_S8 (2*S8_CHUNK + 1024)

__device__ __forceinline__ void load_chunk_s8(u32 buf,
    const char* Ah, const char* Al, const char* Bh, const char* Bl,
    int c0, int t)
{
    #pragma unroll
    for (int j = 0; j < 4; ++j) {
        int idx = t + 256 * j; int row = idx >> 3, g = idx & 7;
        cp16(buf + S8_AH + SW128(row*128 + g*16), Ah + (size_t)row*Cn + c0 + g*16);
    }
    #pragma unroll
    for (int j = 0; j < 4; ++j) {
        int idx = t + 256 * j; int row = idx >> 3, g = idx & 7;
        cp16(buf + S8_AL + SW128(row*128 + g*16), Al + (size_t)row*Cn + c0 + g*16);
    }
    #pragma unroll
    for (int j = 0; j < 4; ++j) {
        int idx = t + 256 * j; int row = idx >> 3, g = idx & 7;
        cp16(buf + S8_BH + SW128(row*128 + g*16), Bh + (size_t)row*Cn + c0 + g*16);
    }
    #pragma unroll
    for (int j = 0; j < 4; ++j) {
        int idx = t + 256 * j; int row = idx >> 3, g = idx & 7;
        cp16(buf + S8_BL + SW128(row*128 + g*16), Bl + (size_t)row*Cn + c0 + g*16);
    }
    CP_COMMIT();
}

__global__ __launch_bounds__(256, 1)
void scores_kernel()
{
    extern __shared__ __align__(1024) char dsm[];
    u32 sb0  = smem_u32(dsm);
    u32 base = (sb0 + 1023) & ~1023u;
    char* alig = dsm + (base - sb0);
    int t = threadIdx.x, wid = t >> 5, lane = t & 31;
    int warp_m = wid & 1, warp_n = wid >> 1;

    int b = blockIdx.z, m0 = blockIdx.x * 128, n0 = blockIdx.y * 128;
    const char* Ah = g_Q8h + ((size_t)(b * Sn + m0)) * Cn;
    const char* Al = g_Q8l + ((size_t)(b * Sn + m0)) * Cn;
    const char* Bh = g_K8h + ((size_t)(b * Sn + n0)) * Cn;
    const char* Bl = g_K8l + ((size_t)(b * Sn + n0)) * Cn;

    int hh[4][4][4], mx[4][4][4];
    #pragma unroll
    for (int i = 0; i < 4; ++i)
        #pragma unroll
        for (int j = 0; j < 4; ++j)
            #pragma unroll
            for (int k = 0; k < 4; ++k) { hh[i][j][k] = 0; mx[i][j][k] = 0; }

    int a_row = warp_m*64 + (lane & 15);
    int a_ck  = (lane >> 4) & 1;
    int b_row = warp_n*32 + (lane & 7) + ((lane >> 4) << 3);
    int b_ck  = (lane >> 3) & 1;

    load_chunk_s8(base, Ah, Al, Bh, Bl, 0, t);

    for (int kc = 0; kc < 2; ++kc) {
        if (kc + 1 < 2) {
            load_chunk_s8(base + S8_CHUNK, Ah, Al, Bh, Bl, 128, t);
            asm volatile("cp.async.wait_group 1;" ::: "memory");
        } else {
            asm volatile("cp.async.wait_group 0;" ::: "memory");
        }
        __syncthreads();

        u32 buf = base + kc * S8_CHUNK;
        #pragma unroll
        for (int ks = 0; ks < 4; ++ks) {      // 4 x k32 steps per 128-chunk
            u32 ah[4][4], al[4][4];
            #pragma unroll
            for (int mt = 0; mt < 4; ++mt) {
                int off = (a_row + mt*16)*128 + ks*32 + a_ck*16;
                u32 sw = SW128(off);
                LDSM_X4(ah[mt][0], ah[mt][1], ah[mt][2], ah[mt][3], buf + S8_AH + sw);
                LDSM_X4(al[mt][0], al[mt][1], al[mt][2], al[mt][3], buf + S8_AL + sw);
            }
            #pragma unroll
            for (int ng = 0; ng < 2; ++ng) {  // n16 groups (2 per warp)
                int off = (b_row + ng*16)*128 + ks*32 + b_ck*16;
                u32 sw = SW128(off);
                u32 bh[4], bl[4];
                LDSM_X4(bh[0], bh[1], bh[2], bh[3], buf + S8_BH + sw);
                LDSM_X4(bl[0], bl[1], bl[2], bl[3], buf + S8_BL + sw);
                #pragma unroll
                for (int hv = 0; hv < 2; ++hv) {   // n8 halves
                    int nt = ng*2 + hv;
                    #pragma unroll
                    for (int mt = 0; mt < 4; ++mt) {
                        MMA_S8(hh[mt][nt], ah[mt], bh[2*hv], bh[2*hv+1]);
                        MMA_S8(mx[mt][nt], ah[mt], bl[2*hv], bl[2*hv+1]);
                        MMA_S8(mx[mt][nt], al[mt], bh[2*hv], bh[2*hv+1]);
                    }
                }
            }
        }
        __syncthreads();
    }

    // fold int accums to fp32, stage, coalesced write
    float* stage = (float*)alig;               // 128 x 132 floats
    int rg = warp_m*64 + (lane >> 2);
    int cg = warp_n*32 + (lane & 3) * 2;
    #pragma unroll
    for (int mt = 0; mt < 4; ++mt) {
        #pragma unroll
        for (int nt = 0; nt < 4; ++nt) {
            int r = rg + mt*16, c = cg + nt*8;
            float2 lo, hi;
            lo.x = __int2float_rn(hh[mt][nt][0])*FOLD_C1 + __int2float_rn(mx[mt][nt][0])*FOLD_C2;
            lo.y = __int2float_rn(hh[mt][nt][1])*FOLD_C1 + __int2float_rn(mx[mt][nt][1])*FOLD_C2;
            hi.x = __int2float_rn(hh[mt][nt][2])*FOLD_C1 + __int2float_rn(mx[mt][nt][2])*FOLD_C2;
            hi.y = __int2float_rn(hh[mt][nt][3])*FOLD_C1 + __int2float_rn(mx[mt][nt][3])*FOLD_C2;
            *(float2*)&stage[r*132 + c]     = lo;
            *(float2*)&stage[(r+8)*132 + c] = hi;
        }
    }
    __syncthreads();
    float* Sg = g_S + ((size_t)(b * Sn + m0)) * Sn + n0;
    #pragma unroll
    for (int i = t; i < 128*32; i += 256) {
        int row = i >> 5, s4 = i & 31;
        float4 v = *(float4*)&stage[row*132 + s4*4];
        *(float4*)&Sg[(size_t)row * Sn + s4*4] = v;
    }
}

// ==================================================================
// Kernel 4: row softmax over 4096 keys -> normalized P as fp16
// ==================================================================
__global__ __launch_bounds__(256)
void softmax_kernel()
{
    __shared__ float red[8];
    size_t row = blockIdx.x;
    const float* src = g_S + row * (size_t)Sn;
    int t = threadIdx.x, lane = t & 31, w = t >> 5;

    float vals[16];
    #pragma unroll
    for (int j = 0; j < 4; ++j) {
        float4 v = *(const float4*)&src[t*16 + j*4];
        vals[j*4+0] = v.x; vals[j*4+1] = v.y; vals[j*4+2] = v.z; vals[j*4+3] = v.w;
    }
    float m = vals[0];
    #pragma unroll
    for (int i = 1; i < 16; ++i) m = fmaxf(m, vals[i]);
    #pragma unroll
    for (int off = 16; off > 0; off >>= 1)
        m = fmaxf(m, __shfl_xor_sync(0xffffffffu, m, off));
    if (lane == 0) red[w] = m;
    __syncthreads();
    m = red[0];
    #pragma unroll
    for (int i = 1; i < 8; ++i) m = fmaxf(m, red[i]);
    __syncthreads();

    float s = 0.f;
    #pragma unroll
    for (int i = 0; i < 16; ++i) { vals[i] = __expf(vals[i] - m); s += vals[i]; }
    #pragma unroll
    for (int off = 16; off > 0; off >>= 1)
        s += __shfl_xor_sync(0xffffffffu, s, off);
    if (lane == 0) red[w] = s;
    __syncthreads();
    s = red[0];
    #pragma unroll
    for (int i = 1; i < 8; ++i) s += red[i];
    float inv = 1.0f / s;

    union { __half h[16]; uint4 q[2]; } H;
    #pragma unroll
    for (int i = 0; i < 16; ++i)
        H.h[i] = __float2half_rn(vals[i] * inv);
    size_t o = row * (size_t)Sn + t * 16;
    *(uint4*)&g_P[o]     = H.q[0];
    *(uint4*)&g_P[o + 8] = H.q[1];
}

// ==================================================================
// Kernel 5: attended = P @ V (single-term fp16), sigmoid, store.
// Block tile 128(M) x 256(N=En), chunks of 64 keys, double-buffered.
// ==================================================================
#define PV_OFF_A 0
#define PV_OFF_B (16*1024)
#define PV_CHUNK (48*1024)
#define SMEM_PV  (2*PV_CHUNK + 1024)

__device__ __forceinline__ void load_pv(u32 buf,
    const __half* A, const __half* B, int c0, int t)
{
    #pragma unroll
    for (int j = 0; j < 4; ++j) {      // P: 128 rows x 8 segs
        int idx = t + 256 * j; int row = idx >> 3, g = idx & 7;
        cp16(buf + PV_OFF_A + SW128(row*128 + g*16), A + (size_t)row*Sn + c0 + g*8);
    }
    #pragma unroll
    for (int j = 0; j < 8; ++j) {      // Vt: 256 rows x 8 segs
        int idx = t + 256 * j; int row = idx >> 3, g = idx & 7;
        cp16(buf + PV_OFF_B + SW128(row*128 + g*16), B + (size_t)row*Sn + c0 + g*8);
    }
    CP_COMMIT();
}

__global__ __launch_bounds__(256, 1)
void pv_kernel(float* __restrict__ out)
{
    extern __shared__ __align__(1024) char dsm[];
    u32 sb0  = smem_u32(dsm);
    u32 base = (sb0 + 1023) & ~1023u;
    int t = threadIdx.x, wid = t >> 5, lane = t & 31;
    int warp_m = wid & 1, warp_n = wid >> 1;

    int b = blockIdx.z, m0 = blockIdx.x * 128;
    const __half* A = g_P + ((size_t)b * Sn + m0) * Sn;
    const __half* B = g_Vt + (size_t)b * En * Sn;

    float acc[4][8][4];
    #pragma unroll
    for (int i = 0; i < 4; ++i)
        #pragma unroll
        for (int j = 0; j < 8; ++j)
            #pragma unroll
            for (int k = 0; k < 4; ++k) acc[i][j][k] = 0.f;

    int a_row = warp_m*64 + (lane & 15);
    int a_ck  = (lane >> 4) & 1;
    int b_row = warp_n*64 + (lane & 7) + ((lane >> 4) << 3);
    int b_ck  = (lane >> 3) & 1;

    const int NCHUNK = Sn / 64;
    load_pv(base, A, B, 0, t);

    for (int kc = 0; kc < NCHUNK; ++kc) {
        if (kc + 1 < NCHUNK) {
            load_pv(base + ((kc+1)&1)*PV_CHUNK, A, B, (kc+1)*64, t);
            asm volatile("cp.async.wait_group 1;" ::: "memory");
        } else {
            asm volatile("cp.async.wait_group 0;" ::: "memory");
        }
        __syncthreads();

        u32 buf = base + (kc & 1) * PV_CHUNK;
        #pragma unroll
        for (int ks = 0; ks < 4; ++ks) {
            u32 af[4][4];
            #pragma unroll
            for (int mt = 0; mt < 4; ++mt) {
                int off = (a_row + mt*16)*128 + (2*ks + a_ck)*16;
                LDSM_X4(af[mt][0], af[mt][1], af[mt][2], af[mt][3],
                        buf + PV_OFF_A + SW128(off));
            }
            #pragma unroll
            for (int np = 0; np < 4; ++np) {
                int off = (b_row + np*16)*128 + (2*ks + b_ck)*16;
                u32 bf[4];
                LDSM_X4(bf[0], bf[1], bf[2], bf[3], buf + PV_OFF_B + SW128(off));
                #pragma unroll
                for (int mt = 0; mt < 4; ++mt) {
                    #pragma unroll
                    for (int j = 0; j < 2; ++j)
                        MMA_F16(acc[mt][np*2+j], af[mt], bf[2*j], bf[2*j+1]);
                }
            }
        }
        __syncthreads();
    }

    float* Og = out + ((size_t)(b * Sn + m0)) * En;
    int rg = warp_m*64 + (lane >> 2);
    int cg = warp_n*64 + (lane & 3) * 2;
    #pragma unroll
    for (int mt = 0; mt < 4; ++mt) {
        #pragma unroll
        for (int nt = 0; nt < 8; ++nt) {
            int r = rg + mt*16, c = cg + nt*8;
            float2 lo, hi;
            lo.x = 1.0f / (1.0f + __expf(-acc[mt][nt][0]));
            lo.y = 1.0f / (1.0f + __expf(-acc[mt][nt][1]));
            hi.x = 1.0f / (1.0f + __expf(-acc[mt][nt][2]));
            hi.y = 1.0f / (1.0f + __expf(-acc[mt][nt][3]));
            *(float2*)&Og[(size_t)r * En + c]       = lo;
            *(float2*)&Og[(size_t)(r + 8) * En + c] = hi;
        }
    }
}

// ==================================================================
// Launch
// ==================================================================
extern "C" void kernel_launch(void* const* d_in, const int* in_sizes, int n_in,
                              void* d_out, int out_size)
{
    const float* x  = (const float*)d_in[0];
    const float* Wq = (const float*)d_in[1];
    const float* bq = (const float*)d_in[2];
    const float* Wk = (const float*)d_in[3];
    const float* bk = (const float*)d_in[4];
    const float* Wv = (const float*)d_in[5];
    const float* bv = (const float*)d_in[6];
    float* out = (float*)d_out;

    cudaFuncSetAttribute(scores_kernel,
        cudaFuncAttributeMaxDynamicSharedMemorySize, SMEM_S8);
    cudaFuncSetAttribute(pv_kernel,
        cudaFuncAttributeMaxDynamicSharedMemorySize, SMEM_PV);

    qkv_proj_kernel<<<dim3(128, 12), 256>>>(x, Wq, bq, Wk, bk, Wv, bv);
    conv_v_kernel<<<dim3(128, 8, 4), dim3(32, 8)>>>();
    scores_kernel<<<dim3(32, 32, 4), 256, SMEM_S8>>>();
    softmax_kernel<<<16384, 256>>>();
    pv_kernel<<<dim3(32, 1, 4), 256, SMEM_PV>>>(out);
}

// round 6
// speedup vs baseline: 1.9448x; 1.9448x over previous
#include <cuda_runtime.h>
#include <cuda_bf16.h>
#include <cuda_fp16.h>
#include <math.h>
#include <stdint.h>

#define Bn 4
#define Sn 4096
#define Cn 256
#define En 256

typedef unsigned int u32;
typedef unsigned long long u64;

// ------------------------------------------------------------------
// Static device scratch (no allocation allowed)
// ------------------------------------------------------------------
__device__ float g_V[Bn * Sn * En];
__device__ __nv_bfloat16 g_Qh[Bn * Sn * Cn];
__device__ __nv_bfloat16 g_Ql[Bn * Sn * Cn];
__device__ __nv_bfloat16 g_Kh[Bn * Sn * Cn];
__device__ __nv_bfloat16 g_Kl[Bn * Sn * Cn];
__device__ __half g_Vt[Bn * En * Sn];        // V transposed fp16: [b][e][s]

// ------------------------------------------------------------------
// helpers
// ------------------------------------------------------------------
__device__ __forceinline__ u32 smem_u32(const void* p) {
    u32 a;
    asm("{ .reg .u64 t; cvta.to.shared.u64 t, %1; cvt.u32.u64 %0, t; }"
        : "=r"(a) : "l"(p));
    return a;
}
#define SW128(o) ((o) ^ (((o) >> 3) & 0x70))

__device__ __forceinline__ void cp16(u32 dst, const void* src) {
    asm volatile("cp.async.cg.shared.global [%0], [%1], 16;" :: "r"(dst), "l"(src));
}
#define CP_COMMIT() asm volatile("cp.async.commit_group;" ::: "memory")
#define CP_WAIT(n)  asm volatile("cp.async.wait_group %0;" :: "n"(n) : "memory")

#define LDSM_X4(r0, r1, r2, r3, addr)                                        \
    asm volatile("ldmatrix.sync.aligned.m8n8.x4.shared.b16 {%0,%1,%2,%3}, [%4];" \
                 : "=r"(r0), "=r"(r1), "=r"(r2), "=r"(r3) : "r"(addr))

#define MMA_BF16(d, a, b0, b1)                                               \
    asm volatile("mma.sync.aligned.m16n8k16.row.col.f32.bf16.bf16.f32 "      \
                 "{%0,%1,%2,%3}, {%4,%5,%6,%7}, {%8,%9}, {%0,%1,%2,%3};"     \
                 : "+f"((d)[0]), "+f"((d)[1]), "+f"((d)[2]), "+f"((d)[3])    \
                 : "r"((a)[0]), "r"((a)[1]), "r"((a)[2]), "r"((a)[3]),       \
                   "r"(b0), "r"(b1))

#define MMA_F16(d, a, b0, b1)                                                \
    asm volatile("mma.sync.aligned.m16n8k16.row.col.f32.f16.f16.f32 "        \
                 "{%0,%1,%2,%3}, {%4,%5,%6,%7}, {%8,%9}, {%0,%1,%2,%3};"     \
                 : "+f"((d)[0]), "+f"((d)[1]), "+f"((d)[2]), "+f"((d)[3])    \
                 : "r"((a)[0]), "r"((a)[1]), "r"((a)[2]), "r"((a)[3]),       \
                   "r"(b0), "r"(b1))

__device__ __forceinline__ u32 h2u(float a, float b) {
    __half2 h = __floats2half2_rn(a, b);
    return *(u32*)&h;
}

// f32x2 helpers for the FFMA QKV kernel
__device__ __forceinline__ u64 pk2(float lo, float hi) {
    u64 r; asm("mov.b64 %0, {%1,%2};" : "=l"(r) : "f"(lo), "f"(hi)); return r;
}
__device__ __forceinline__ void fma2(u64& d, u64 a, u64 b) {
    asm("fma.rn.f32x2 %0, %1, %2, %0;" : "+l"(d) : "l"(a), "l"(b));
}
__device__ __forceinline__ void upk2(u64 v, float& lo, float& hi) {
    asm("mov.b64 {%0,%1}, %2;" : "=f"(lo), "=f"(hi) : "l"(v));
}

// ==================================================================
// Kernel 1: QKV projections (FFMA). Q/K written as bf16 hi/lo,
// V written fp32 (transposed+converted later).
// ==================================================================
__global__ __launch_bounds__(256)
void qkv_proj_kernel(const float* __restrict__ x,
                     const float* __restrict__ Wq, const float* __restrict__ bq,
                     const float* __restrict__ Wk, const float* __restrict__ bk,
                     const float* __restrict__ Wv, const float* __restrict__ bv)
{
    __shared__ float Xs[16][132];
    __shared__ float Wsh[16][64];

    int t  = threadIdx.x;
    int m0 = blockIdx.x * 128;
    int nb = blockIdx.y;
    int which = nb >> 2;
    int n0 = (nb & 3) * 64;

    const float* W; const float* bias;
    if (which == 0)      { W = Wq; bias = bq; }
    else if (which == 1) { W = Wk; bias = bk; }
    else                 { W = Wv; bias = bv; }

    int tr = t >> 4, tc = t & 15;

    u64 acc[8][2];
    #pragma unroll
    for (int i = 0; i < 8; i++) { acc[i][0] = 0ull; acc[i][1] = 0ull; }

    for (int kc = 0; kc < Cn; kc += 16) {
        __syncthreads();
        for (int i = t; i < 512; i += 256) {
            int row = i >> 2, seg = i & 3;
            float4 v = *(const float4*)&x[(size_t)(m0 + row) * Cn + kc + seg * 4];
            Xs[seg*4+0][row] = v.x; Xs[seg*4+1][row] = v.y;
            Xs[seg*4+2][row] = v.z; Xs[seg*4+3][row] = v.w;
        }
        {
            int row = t >> 4, seg = t & 15;
            *(float4*)&Wsh[row][seg*4] =
                *(const float4*)&W[(size_t)(kc + row) * 256 + n0 + seg * 4];
        }
        __syncthreads();

        #pragma unroll
        for (int k = 0; k < 16; ++k) {
            float4 a0 = *(float4*)&Xs[k][tr*8];
            float4 a1 = *(float4*)&Xs[k][tr*8 + 4];
            float4 bb = *(float4*)&Wsh[k][tc*4];
            u64 b01 = pk2(bb.x, bb.y), b23 = pk2(bb.z, bb.w);
            float av[8] = {a0.x,a0.y,a0.z,a0.w,a1.x,a1.y,a1.z,a1.w};
            #pragma unroll
            for (int i = 0; i < 8; ++i) {
                u64 ad = pk2(av[i], av[i]);
                fma2(acc[i][0], ad, b01);
                fma2(acc[i][1], ad, b23);
            }
        }
    }

    float4 bb4 = *(const float4*)&bias[n0 + tc*4];
    #pragma unroll
    for (int i = 0; i < 8; ++i) {
        float v[4];
        upk2(acc[i][0], v[0], v[1]);
        upk2(acc[i][1], v[2], v[3]);
        v[0] += bb4.x; v[1] += bb4.y; v[2] += bb4.z; v[3] += bb4.w;
        size_t idx = (size_t)(m0 + tr*8 + i) * 256 + n0 + tc*4;
        if (which == 2) {
            float4 r; r.x = v[0]; r.y = v[1]; r.z = v[2]; r.w = v[3];
            *(float4*)&g_V[idx] = r;
        } else {
            union { __nv_bfloat16 h[4]; uint2 q; } H, L;
            #pragma unroll
            for (int j = 0; j < 4; ++j) {
                H.h[j] = __float2bfloat16(v[j]);
                L.h[j] = __float2bfloat16(v[j] - __bfloat162float(H.h[j]));
            }
            if (which == 0) {
                *(uint2*)&g_Qh[idx] = H.q;
                *(uint2*)&g_Ql[idx] = L.q;
            } else {
                *(uint2*)&g_Kh[idx] = H.q;
                *(uint2*)&g_Kl[idx] = L.q;
            }
        }
    }
}

// ==================================================================
// Kernel 2: transpose + convert V -> Vt[b][e][s] fp16
// ==================================================================
__global__ __launch_bounds__(256)
void conv_v_kernel()
{
    __shared__ float tile[32][33];
    int b  = blockIdx.z;
    int s0 = blockIdx.x * 32, e0 = blockIdx.y * 32;
    int tx = threadIdx.x, ty = threadIdx.y;

    #pragma unroll
    for (int j = ty; j < 32; j += 8)
        tile[j][tx] = g_V[((size_t)(b * Sn + s0 + j)) * En + e0 + tx];
    __syncthreads();
    #pragma unroll
    for (int j = ty; j < 32; j += 8) {
        float v = tile[tx][j];   // = V[s0+tx][e0+j]
        size_t o = ((size_t)(b * En + e0 + j)) * Sn + s0 + tx;
        g_Vt[o] = __float2half_rn(v);
    }
}

// ==================================================================
// Kernel 3: fused flash attention + sigmoid.
// Block = 128 q-rows x full 4096 keys x E=256. 8 warps, each warp
// owns 16 q-rows. K streamed in 64-key tiles (bf16 hi/lo, 3-term
// MMA); P stays in registers (C-frag == A-frag layout); V fp16.
//
// smem: Q hi/lo 128KB resident + K tile 64KB + V tile 32KB = 224KB.
// ==================================================================
#define FK_QH 0
#define FK_QL (64*1024)
#define FK_KH (128*1024)
#define FK_KL (160*1024)
#define FK_VT (192*1024)
#define SMEM_FK (224*1024 + 1024)

__device__ __forceinline__ void load_k_tile(u32 base,
    const __nv_bfloat16* Kh, const __nv_bfloat16* Kl, int s0, int t)
{
    #pragma unroll
    for (int j = 0; j < 8; ++j) {
        int idx = t + 256*j;               // 2048 ops: 4cc x 64rows x 8segs
        int cc = idx >> 9, rr = (idx >> 3) & 63, g = idx & 7;
        cp16(base + FK_KH + cc*8192 + SW128(rr*128 + g*16),
             Kh + (size_t)(s0 + rr)*Cn + cc*64 + g*8);
    }
    #pragma unroll
    for (int j = 0; j < 8; ++j) {
        int idx = t + 256*j;
        int cc = idx >> 9, rr = (idx >> 3) & 63, g = idx & 7;
        cp16(base + FK_KL + cc*8192 + SW128(rr*128 + g*16),
             Kl + (size_t)(s0 + rr)*Cn + cc*64 + g*8);
    }
    CP_COMMIT();
}

__device__ __forceinline__ void load_v_tile(u32 base,
    const __half* Vt, int s0, int t)
{
    #pragma unroll
    for (int j = 0; j < 8; ++j) {
        int idx = t + 256*j;               // 2048 ops: 256 rows x 8 segs
        int rr = idx >> 3, g = idx & 7;
        cp16(base + FK_VT + SW128(rr*128 + g*16),
             Vt + (size_t)rr*Sn + s0 + g*8);
    }
    CP_COMMIT();
}

__global__ __launch_bounds__(256, 1)
void flash_kernel(float* __restrict__ out)
{
    extern __shared__ __align__(1024) char dsm[];
    u32 sb0 = smem_u32(dsm);
    u32 base = (sb0 + 1023) & ~1023u;
    int t = threadIdx.x, wid = t >> 5, lane = t & 31;
    int b = blockIdx.y, m0 = blockIdx.x * 128;

    const __nv_bfloat16* Qh = g_Qh + ((size_t)(b*Sn + m0))*Cn;
    const __nv_bfloat16* Ql = g_Ql + ((size_t)(b*Sn + m0))*Cn;
    const __nv_bfloat16* Kh = g_Kh + (size_t)b*Sn*Cn;
    const __nv_bfloat16* Kl = g_Kl + (size_t)b*Sn*Cn;
    const __half*        Vt = g_Vt + (size_t)b*En*Sn;

    // Q load: one cp.async group (hi + lo)
    #pragma unroll
    for (int j = 0; j < 16; ++j) {
        int idx = t + 256*j;               // 4096: 4cc x 128rows x 8segs
        int cc = idx >> 10, rr = (idx >> 3) & 127, g = idx & 7;
        cp16(base + FK_QH + cc*16384 + SW128(rr*128 + g*16),
             Qh + (size_t)rr*Cn + cc*64 + g*8);
    }
    #pragma unroll
    for (int j = 0; j < 16; ++j) {
        int idx = t + 256*j;
        int cc = idx >> 10, rr = (idx >> 3) & 127, g = idx & 7;
        cp16(base + FK_QL + cc*16384 + SW128(rr*128 + g*16),
             Ql + (size_t)rr*Cn + cc*64 + g*8);
    }
    CP_COMMIT();
    load_k_tile(base, Kh, Kl, 0, t);

    float o[32][4];
    #pragma unroll
    for (int i = 0; i < 32; ++i)
        #pragma unroll
        for (int j = 0; j < 4; ++j) o[i][j] = 0.f;
    float m0r = -INFINITY, m1r = -INFINITY, l0r = 0.f, l1r = 0.f;

    int a_row = wid*16 + (lane & 15);
    int a_ck  = (lane >> 4) & 1;
    int b_row = (lane & 7) + ((lane >> 4) << 3);
    int b_ck  = (lane >> 3) & 1;

    for (int kt = 0; kt < 64; ++kt) {
        load_v_tile(base, Vt, kt*64, t);
        CP_WAIT(1);                         // Q + K(kt) complete
        __syncthreads();

        // ---- QK: S tile 16(rows/warp) x 64 keys, bf16 3-term ----
        float s[8][4];
        #pragma unroll
        for (int i = 0; i < 8; ++i)
            #pragma unroll
            for (int j = 0; j < 4; ++j) s[i][j] = 0.f;

        #pragma unroll
        for (int ks = 0; ks < 16; ++ks) {
            int cc = ks >> 2, kl2 = ks & 3;
            u32 swA = SW128((u32)(a_row*128 + (2*kl2 + a_ck)*16));
            u32 ah[4], al[4];
            LDSM_X4(ah[0], ah[1], ah[2], ah[3], base + FK_QH + cc*16384 + swA);
            LDSM_X4(al[0], al[1], al[2], al[3], base + FK_QL + cc*16384 + swA);
            #pragma unroll
            for (int ng = 0; ng < 4; ++ng) {
                u32 swB = SW128((u32)((b_row + ng*16)*128 + (2*kl2 + b_ck)*16));
                u32 bh[4], bl[4];
                LDSM_X4(bh[0], bh[1], bh[2], bh[3], base + FK_KH + cc*8192 + swB);
                LDSM_X4(bl[0], bl[1], bl[2], bl[3], base + FK_KL + cc*8192 + swB);
                #pragma unroll
                for (int hv = 0; hv < 2; ++hv) {
                    MMA_BF16(s[ng*2+hv], ah, bh[2*hv], bh[2*hv+1]);
                    MMA_BF16(s[ng*2+hv], ah, bl[2*hv], bl[2*hv+1]);
                    MMA_BF16(s[ng*2+hv], al, bh[2*hv], bh[2*hv+1]);
                }
            }
        }
        __syncthreads();                    // all warps done reading K tile
        if (kt + 1 < 64) load_k_tile(base, Kh, Kl, (kt+1)*64, t);

        // ---- online softmax on 2 owned rows ----
        float mx0 = s[0][0], mx1 = s[0][2];
        #pragma unroll
        for (int nt = 0; nt < 8; ++nt) {
            mx0 = fmaxf(mx0, fmaxf(s[nt][0], s[nt][1]));
            mx1 = fmaxf(mx1, fmaxf(s[nt][2], s[nt][3]));
        }
        mx0 = fmaxf(mx0, __shfl_xor_sync(0xffffffffu, mx0, 1));
        mx0 = fmaxf(mx0, __shfl_xor_sync(0xffffffffu, mx0, 2));
        mx1 = fmaxf(mx1, __shfl_xor_sync(0xffffffffu, mx1, 1));
        mx1 = fmaxf(mx1, __shfl_xor_sync(0xffffffffu, mx1, 2));
        float mn0 = fmaxf(m0r, mx0), mn1 = fmaxf(m1r, mx1);
        float sc0 = __expf(m0r - mn0), sc1 = __expf(m1r - mn1);
        m0r = mn0; m1r = mn1;

        float sum0 = 0.f, sum1 = 0.f;
        #pragma unroll
        for (int nt = 0; nt < 8; ++nt) {
            s[nt][0] = __expf(s[nt][0] - mn0);
            s[nt][1] = __expf(s[nt][1] - mn0);
            s[nt][2] = __expf(s[nt][2] - mn1);
            s[nt][3] = __expf(s[nt][3] - mn1);
            sum0 += s[nt][0] + s[nt][1];
            sum1 += s[nt][2] + s[nt][3];
        }
        sum0 += __shfl_xor_sync(0xffffffffu, sum0, 1);
        sum0 += __shfl_xor_sync(0xffffffffu, sum0, 2);
        sum1 += __shfl_xor_sync(0xffffffffu, sum1, 1);
        sum1 += __shfl_xor_sync(0xffffffffu, sum1, 2);
        l0r = l0r * sc0 + sum0;
        l1r = l1r * sc1 + sum1;

        if (!__all_sync(0xffffffffu, (sc0 == 1.f) & (sc1 == 1.f))) {
            #pragma unroll
            for (int nb = 0; nb < 32; ++nb) {
                o[nb][0] *= sc0; o[nb][1] *= sc0;
                o[nb][2] *= sc1; o[nb][3] *= sc1;
            }
        }

        // ---- pack P (C-frag -> A-frag, fp16) ----
        u32 af[4][4];
        #pragma unroll
        for (int ka = 0; ka < 4; ++ka) {
            af[ka][0] = h2u(s[2*ka][0],   s[2*ka][1]);
            af[ka][1] = h2u(s[2*ka][2],   s[2*ka][3]);
            af[ka][2] = h2u(s[2*ka+1][0], s[2*ka+1][1]);
            af[ka][3] = h2u(s[2*ka+1][2], s[2*ka+1][3]);
        }

        if (kt + 1 < 64) { CP_WAIT(1); } else { CP_WAIT(0); }   // V(kt) done
        __syncthreads();

        // ---- PV: O(16 x 256) += P(16 x 64) @ V(64 x 256) ----
        #pragma unroll
        for (int ka = 0; ka < 4; ++ka) {
            #pragma unroll
            for (int nb = 0; nb < 16; ++nb) {
                u32 swV = SW128((u32)((b_row + nb*16)*128 + (2*ka + b_ck)*16));
                u32 bf[4];
                LDSM_X4(bf[0], bf[1], bf[2], bf[3], base + FK_VT + swV);
                MMA_F16(o[nb*2],   af[ka], bf[0], bf[1]);
                MMA_F16(o[nb*2+1], af[ka], bf[2], bf[3]);
            }
        }
        __syncthreads();                    // all done reading V tile
    }

    // ---- epilogue: normalize, sigmoid, store ----
    float i0 = 1.f / l0r, i1 = 1.f / l1r;
    int row0 = m0 + wid*16 + (lane >> 2);
    float* O0 = out + ((size_t)b*Sn + row0) * En;
    #pragma unroll
    for (int nb = 0; nb < 32; ++nb) {
        int c = nb*8 + (lane & 3)*2;
        float2 v0, v1;
        v0.x = 1.f / (1.f + __expf(-o[nb][0] * i0));
        v0.y = 1.f / (1.f + __expf(-o[nb][1] * i0));
        v1.x = 1.f / (1.f + __expf(-o[nb][2] * i1));
        v1.y = 1.f / (1.f + __expf(-o[nb][3] * i1));
        *(float2*)&O0[c]          = v0;
        *(float2*)&O0[8*En + c]   = v1;
    }
}

// ==================================================================
// Launch
// ==================================================================
extern "C" void kernel_launch(void* const* d_in, const int* in_sizes, int n_in,
                              void* d_out, int out_size)
{
    const float* x  = (const float*)d_in[0];
    const float* Wq = (const float*)d_in[1];
    const float* bq = (const float*)d_in[2];
    const float* Wk = (const float*)d_in[3];
    const float* bk = (const float*)d_in[4];
    const float* Wv = (const float*)d_in[5];
    const float* bv = (const float*)d_in[6];
    float* out = (float*)d_out;

    cudaFuncSetAttribute(flash_kernel,
        cudaFuncAttributeMaxDynamicSharedMemorySize, SMEM_FK);

    qkv_proj_kernel<<<dim3(128, 12), 256>>>(x, Wq, bq, Wk, bk, Wv, bv);
    conv_v_kernel<<<dim3(128, 8, 4), dim3(32, 8)>>>();
    flash_kernel<<<dim3(32, 4), 256, SMEM_FK>>>(out);
}

// round 7
// speedup vs baseline: 2.2639x; 1.1641x over previous
#include <cuda_runtime.h>
#include <cuda_bf16.h>
#include <cuda_fp16.h>
#include <math.h>
#include <stdint.h>

#define Bn 4
#define Sn 4096
#define Cn 256
#define En 256
#define Mtot (Bn * Sn)

typedef unsigned int u32;
typedef unsigned long long u64;

// ------------------------------------------------------------------
// Static device scratch (no allocation allowed)
// ------------------------------------------------------------------
__device__ __nv_bfloat16 g_xh[Mtot * Cn];
__device__ __nv_bfloat16 g_xl[Mtot * Cn];
__device__ __nv_bfloat16 g_Wth[3 * Cn * Cn];   // Wt[which][n][k]
__device__ __nv_bfloat16 g_Wtl[3 * Cn * Cn];
__device__ __nv_bfloat16 g_Qh[Mtot * Cn];
__device__ __nv_bfloat16 g_Ql[Mtot * Cn];
__device__ __nv_bfloat16 g_Kh[Mtot * Cn];
__device__ __nv_bfloat16 g_Kl[Mtot * Cn];
__device__ __half g_Vt[Bn * En * Sn];          // V transposed fp16: [b][e][s]

// ------------------------------------------------------------------
// helpers
// ------------------------------------------------------------------
__device__ __forceinline__ u32 smem_u32(const void* p) {
    u32 a;
    asm("{ .reg .u64 t; cvta.to.shared.u64 t, %1; cvt.u32.u64 %0, t; }"
        : "=r"(a) : "l"(p));
    return a;
}
#define SW128(o) ((o) ^ (((o) >> 3) & 0x70))

__device__ __forceinline__ void cp16(u32 dst, const void* src) {
    asm volatile("cp.async.cg.shared.global [%0], [%1], 16;" :: "r"(dst), "l"(src));
}
#define CP_COMMIT() asm volatile("cp.async.commit_group;" ::: "memory")
#define CP_WAIT(n)  asm volatile("cp.async.wait_group %0;" :: "n"(n) : "memory")

#define LDSM_X4(r0, r1, r2, r3, addr)                                        \
    asm volatile("ldmatrix.sync.aligned.m8n8.x4.shared.b16 {%0,%1,%2,%3}, [%4];" \
                 : "=r"(r0), "=r"(r1), "=r"(r2), "=r"(r3) : "r"(addr))

#define MMA_BF16(d, a, b0, b1)                                               \
    asm volatile("mma.sync.aligned.m16n8k16.row.col.f32.bf16.bf16.f32 "      \
                 "{%0,%1,%2,%3}, {%4,%5,%6,%7}, {%8,%9}, {%0,%1,%2,%3};"     \
                 : "+f"((d)[0]), "+f"((d)[1]), "+f"((d)[2]), "+f"((d)[3])    \
                 : "r"((a)[0]), "r"((a)[1]), "r"((a)[2]), "r"((a)[3]),       \
                   "r"(b0), "r"(b1))

#define MMA_F16(d, a, b0, b1)                                                \
    asm volatile("mma.sync.aligned.m16n8k16.row.col.f32.f16.f16.f32 "        \
                 "{%0,%1,%2,%3}, {%4,%5,%6,%7}, {%8,%9}, {%0,%1,%2,%3};"     \
                 : "+f"((d)[0]), "+f"((d)[1]), "+f"((d)[2]), "+f"((d)[3])    \
                 : "r"((a)[0]), "r"((a)[1]), "r"((a)[2]), "r"((a)[3]),       \
                   "r"(b0), "r"(b1))

__device__ __forceinline__ u32 h2u(float a, float b) {
    __half2 h = __floats2half2_rn(a, b);
    return *(u32*)&h;
}

// ==================================================================
// Kernel P1: split x into bf16 hi/lo planes
// ==================================================================
__global__ __launch_bounds__(256)
void split_x_kernel(const float* __restrict__ x)
{
    size_t i = ((size_t)blockIdx.x * 256 + threadIdx.x) * 4;
    float4 v = *(const float4*)&x[i];
    float a[4] = {v.x, v.y, v.z, v.w};
    union { __nv_bfloat16 h[4]; uint2 q; } H, L;
    #pragma unroll
    for (int j = 0; j < 4; ++j) {
        H.h[j] = __float2bfloat16(a[j]);
        L.h[j] = __float2bfloat16(a[j] - __bfloat162float(H.h[j]));
    }
    *(uint2*)&g_xh[i] = H.q;
    *(uint2*)&g_xl[i] = L.q;
}

// ==================================================================
// Kernel P2: transpose + split W -> Wt[which][n][k] bf16 hi/lo
// ==================================================================
__global__ __launch_bounds__(256)
void prep_w_kernel(const float* __restrict__ Wq,
                   const float* __restrict__ Wk,
                   const float* __restrict__ Wv)
{
    __shared__ float tile[32][33];
    int which = blockIdx.z;
    const float* W = (which == 0) ? Wq : (which == 1) ? Wk : Wv;
    int k0 = blockIdx.x * 32, n0 = blockIdx.y * 32;
    int tx = threadIdx.x, ty = threadIdx.y;

    #pragma unroll
    for (int j = ty; j < 32; j += 8)
        tile[j][tx] = W[(size_t)(k0 + j) * Cn + n0 + tx];
    __syncthreads();
    #pragma unroll
    for (int j = ty; j < 32; j += 8) {
        float v = tile[tx][j];     // = W[k0+tx][n0+j]
        __nv_bfloat16 hi = __float2bfloat16(v);
        __nv_bfloat16 lo = __float2bfloat16(v - __bfloat162float(hi));
        size_t o = (size_t)which * Cn * Cn + (size_t)(n0 + j) * Cn + k0 + tx;
        g_Wth[o] = hi;
        g_Wtl[o] = lo;
    }
}

// ==================================================================
// Kernel P3: QKV projection GEMM (bf16 3-term mma).
// Block tile 128(M) x 256(N), K=256 in 4 double-buffered 64-chunks.
// grid (128 mtiles, 3 matrices). 8 warps: 2M x 4N, warp tile 64x64.
// Epilogue: Q/K -> bias + bf16 hi/lo planes; V -> bias + fp16,
// transposed via smem stage into g_Vt[b][e][s].
// ==================================================================
#define OFF_AH 0
#define OFF_AL (16*1024)
#define OFF_BH (32*1024)
#define OFF_BL (64*1024)
#define CHUNK_BYTES (96*1024)
#define SMEM_GEMM (2*CHUNK_BYTES + 1024)

__device__ __forceinline__ void load_chunk(u32 buf,
    const __nv_bfloat16* Ah, const __nv_bfloat16* Al,
    const __nv_bfloat16* Bh, const __nv_bfloat16* Bl,
    int c0, int t)
{
    #pragma unroll
    for (int j = 0; j < 4; ++j) {
        int idx = t + 256 * j; int row = idx >> 3, g = idx & 7;
        cp16(buf + OFF_AH + SW128(row*128 + g*16), Ah + (size_t)row*Cn + c0 + g*8);
    }
    #pragma unroll
    for (int j = 0; j < 4; ++j) {
        int idx = t + 256 * j; int row = idx >> 3, g = idx & 7;
        cp16(buf + OFF_AL + SW128(row*128 + g*16), Al + (size_t)row*Cn + c0 + g*8);
    }
    #pragma unroll
    for (int j = 0; j < 8; ++j) {
        int idx = t + 256 * j; int row = idx >> 3, g = idx & 7;
        cp16(buf + OFF_BH + SW128(row*128 + g*16), Bh + (size_t)row*Cn + c0 + g*8);
    }
    #pragma unroll
    for (int j = 0; j < 8; ++j) {
        int idx = t + 256 * j; int row = idx >> 3, g = idx & 7;
        cp16(buf + OFF_BL + SW128(row*128 + g*16), Bl + (size_t)row*Cn + c0 + g*8);
    }
    CP_COMMIT();
}

__global__ __launch_bounds__(256, 1)
void qkv_mma_kernel(const float* __restrict__ bq,
                    const float* __restrict__ bk,
                    const float* __restrict__ bv)
{
    extern __shared__ __align__(1024) char dsm[];
    u32 sb0  = smem_u32(dsm);
    u32 base = (sb0 + 1023) & ~1023u;
    char* alig = dsm + (base - sb0);
    int t = threadIdx.x, wid = t >> 5, lane = t & 31;
    int warp_m = wid & 1, warp_n = wid >> 1;

    int m0 = blockIdx.x * 128;
    int which = blockIdx.y;
    const float* bias = (which == 0) ? bq : (which == 1) ? bk : bv;

    const __nv_bfloat16* Ah = g_xh + (size_t)m0 * Cn;
    const __nv_bfloat16* Al = g_xl + (size_t)m0 * Cn;
    const __nv_bfloat16* Bh = g_Wth + (size_t)which * Cn * Cn;
    const __nv_bfloat16* Bl = g_Wtl + (size_t)which * Cn * Cn;

    float acc[4][8][4];
    #pragma unroll
    for (int i = 0; i < 4; ++i)
        #pragma unroll
        for (int j = 0; j < 8; ++j)
            #pragma unroll
            for (int k = 0; k < 4; ++k) acc[i][j][k] = 0.f;

    int a_row = warp_m*64 + (lane & 15);
    int a_ck  = (lane >> 4) & 1;
    int b_row = warp_n*64 + (lane & 7) + ((lane >> 4) << 3);
    int b_ck  = (lane >> 3) & 1;

    load_chunk(base, Ah, Al, Bh, Bl, 0, t);

    for (int kc = 0; kc < 4; ++kc) {
        if (kc + 1 < 4) {
            load_chunk(base + ((kc+1)&1)*CHUNK_BYTES, Ah, Al, Bh, Bl, (kc+1)*64, t);
            asm volatile("cp.async.wait_group 1;" ::: "memory");
        } else {
            asm volatile("cp.async.wait_group 0;" ::: "memory");
        }
        __syncthreads();

        u32 buf = base + (kc & 1) * CHUNK_BYTES;
        #pragma unroll
        for (int ks = 0; ks < 4; ++ks) {
            u32 ah[4][4], al[4][4];
            #pragma unroll
            for (int mt = 0; mt < 4; ++mt) {
                int off = (a_row + mt*16)*128 + (2*ks + a_ck)*16;
                u32 sw = SW128(off);
                LDSM_X4(ah[mt][0], ah[mt][1], ah[mt][2], ah[mt][3], buf + OFF_AH + sw);
                LDSM_X4(al[mt][0], al[mt][1], al[mt][2], al[mt][3], buf + OFF_AL + sw);
            }
            #pragma unroll
            for (int np = 0; np < 4; ++np) {
                int off = (b_row + np*16)*128 + (2*ks + b_ck)*16;
                u32 sw = SW128(off);
                u32 bh[4], bl[4];
                LDSM_X4(bh[0], bh[1], bh[2], bh[3], buf + OFF_BH + sw);
                LDSM_X4(bl[0], bl[1], bl[2], bl[3], buf + OFF_BL + sw);
                #pragma unroll
                for (int mt = 0; mt < 4; ++mt) {
                    #pragma unroll
                    for (int j = 0; j < 2; ++j) {
                        MMA_BF16(acc[mt][np*2+j], ah[mt], bh[2*j], bh[2*j+1]);
                        MMA_BF16(acc[mt][np*2+j], ah[mt], bl[2*j], bl[2*j+1]);
                        MMA_BF16(acc[mt][np*2+j], al[mt], bh[2*j], bh[2*j+1]);
                    }
                }
            }
        }
        __syncthreads();
    }

    // ---- epilogue ----
    int rg = warp_m*64 + (lane >> 2);
    int cg = warp_n*64 + (lane & 3) * 2;

    if (which < 2) {
        __nv_bfloat16* Dh = (which == 0) ? g_Qh : g_Kh;
        __nv_bfloat16* Dl = (which == 0) ? g_Ql : g_Kl;
        #pragma unroll
        for (int mt = 0; mt < 4; ++mt) {
            #pragma unroll
            for (int nt = 0; nt < 8; ++nt) {
                int r = rg + mt*16, c = cg + nt*8;
                float b0 = bias[c], b1 = bias[c+1];
                #pragma unroll
                for (int hv = 0; hv < 2; ++hv) {
                    int rr = r + hv*8;
                    float v0 = acc[mt][nt][hv*2]   + b0;
                    float v1 = acc[mt][nt][hv*2+1] + b1;
                    union { __nv_bfloat16 h[2]; u32 q; } H, L;
                    H.h[0] = __float2bfloat16(v0);
                    L.h[0] = __float2bfloat16(v0 - __bfloat162float(H.h[0]));
                    H.h[1] = __float2bfloat16(v1);
                    L.h[1] = __float2bfloat16(v1 - __bfloat162float(H.h[1]));
                    size_t idx = (size_t)(m0 + rr) * Cn + c;
                    *(u32*)&Dh[idx] = H.q;
                    *(u32*)&Dl[idx] = L.q;
                }
            }
        }
    } else {
        // V: stage fp16 transposed [e][s] then coalesced write to g_Vt
        __half* stage = (__half*)alig;       // [256 e][136 pad]
        #pragma unroll
        for (int mt = 0; mt < 4; ++mt) {
            #pragma unroll
            for (int nt = 0; nt < 8; ++nt) {
                int r = rg + mt*16, c = cg + nt*8;
                float b0 = bias[c], b1 = bias[c+1];
                #pragma unroll
                for (int hv = 0; hv < 2; ++hv) {
                    int rr = r + hv*8;
                    stage[(c)   * 136 + rr] = __float2half_rn(acc[mt][nt][hv*2]   + b0);
                    stage[(c+1) * 136 + rr] = __float2half_rn(acc[mt][nt][hv*2+1] + b1);
                }
            }
        }
        __syncthreads();
        int b = m0 >> 12, s0 = m0 & 4095;
        #pragma unroll
        for (int i = t; i < 256 * 32; i += 256) {
            int e = i >> 5, sseg = i & 31;
            uint2 v;
            v.x = *(u32*)&stage[e*136 + sseg*4];
            v.y = *(u32*)&stage[e*136 + sseg*4 + 2];
            *(uint2*)&g_Vt[((size_t)(b * En + e)) * Sn + s0 + sseg*4] = v;
        }
    }
}

// ==================================================================
// Kernel 3: fused flash attention + sigmoid (unchanged from R6).
// ==================================================================
#define FK_QH 0
#define FK_QL (64*1024)
#define FK_KH (128*1024)
#define FK_KL (160*1024)
#define FK_VT (192*1024)
#define SMEM_FK (224*1024 + 1024)

__device__ __forceinline__ void load_k_tile(u32 base,
    const __nv_bfloat16* Kh, const __nv_bfloat16* Kl, int s0, int t)
{
    #pragma unroll
    for (int j = 0; j < 8; ++j) {
        int idx = t + 256*j;
        int cc = idx >> 9, rr = (idx >> 3) & 63, g = idx & 7;
        cp16(base + FK_KH + cc*8192 + SW128(rr*128 + g*16),
             Kh + (size_t)(s0 + rr)*Cn + cc*64 + g*8);
    }
    #pragma unroll
    for (int j = 0; j < 8; ++j) {
        int idx = t + 256*j;
        int cc = idx >> 9, rr = (idx >> 3) & 63, g = idx & 7;
        cp16(base + FK_KL + cc*8192 + SW128(rr*128 + g*16),
             Kl + (size_t)(s0 + rr)*Cn + cc*64 + g*8);
    }
    CP_COMMIT();
}

__device__ __forceinline__ void load_v_tile(u32 base,
    const __half* Vt, int s0, int t)
{
    #pragma unroll
    for (int j = 0; j < 8; ++j) {
        int idx = t + 256*j;
        int rr = idx >> 3, g = idx & 7;
        cp16(base + FK_VT + SW128(rr*128 + g*16),
             Vt + (size_t)rr*Sn + s0 + g*8);
    }
    CP_COMMIT();
}

__global__ __launch_bounds__(256, 1)
void flash_kernel(float* __restrict__ out)
{
    extern __shared__ __align__(1024) char dsm[];
    u32 sb0 = smem_u32(dsm);
    u32 base = (sb0 + 1023) & ~1023u;
    int t = threadIdx.x, wid = t >> 5, lane = t & 31;
    int b = blockIdx.y, m0 = blockIdx.x * 128;

    const __nv_bfloat16* Qh = g_Qh + ((size_t)(b*Sn + m0))*Cn;
    const __nv_bfloat16* Ql = g_Ql + ((size_t)(b*Sn + m0))*Cn;
    const __nv_bfloat16* Kh = g_Kh + (size_t)b*Sn*Cn;
    const __nv_bfloat16* Kl = g_Kl + (size_t)b*Sn*Cn;
    const __half*        Vt = g_Vt + (size_t)b*En*Sn;

    #pragma unroll
    for (int j = 0; j < 16; ++j) {
        int idx = t + 256*j;
        int cc = idx >> 10, rr = (idx >> 3) & 127, g = idx & 7;
        cp16(base + FK_QH + cc*16384 + SW128(rr*128 + g*16),
             Qh + (size_t)rr*Cn + cc*64 + g*8);
    }
    #pragma unroll
    for (int j = 0; j < 16; ++j) {
        int idx = t + 256*j;
        int cc = idx >> 10, rr = (idx >> 3) & 127, g = idx & 7;
        cp16(base + FK_QL + cc*16384 + SW128(rr*128 + g*16),
             Ql + (size_t)rr*Cn + cc*64 + g*8);
    }
    CP_COMMIT();
    load_k_tile(base, Kh, Kl, 0, t);

    float o[32][4];
    #pragma unroll
    for (int i = 0; i < 32; ++i)
        #pragma unroll
        for (int j = 0; j < 4; ++j) o[i][j] = 0.f;
    float m0r = -INFINITY, m1r = -INFINITY, l0r = 0.f, l1r = 0.f;

    int a_row = wid*16 + (lane & 15);
    int a_ck  = (lane >> 4) & 1;
    int b_row = (lane & 7) + ((lane >> 4) << 3);
    int b_ck  = (lane >> 3) & 1;

    for (int kt = 0; kt < 64; ++kt) {
        load_v_tile(base, Vt, kt*64, t);
        CP_WAIT(1);
        __syncthreads();

        float s[8][4];
        #pragma unroll
        for (int i = 0; i < 8; ++i)
            #pragma unroll
            for (int j = 0; j < 4; ++j) s[i][j] = 0.f;

        #pragma unroll
        for (int ks = 0; ks < 16; ++ks) {
            int cc = ks >> 2, kl2 = ks & 3;
            u32 swA = SW128((u32)(a_row*128 + (2*kl2 + a_ck)*16));
            u32 ah[4], al[4];
            LDSM_X4(ah[0], ah[1], ah[2], ah[3], base + FK_QH + cc*16384 + swA);
            LDSM_X4(al[0], al[1], al[2], al[3], base + FK_QL + cc*16384 + swA);
            #pragma unroll
            for (int ng = 0; ng < 4; ++ng) {
                u32 swB = SW128((u32)((b_row + ng*16)*128 + (2*kl2 + b_ck)*16));
                u32 bh[4], bl[4];
                LDSM_X4(bh[0], bh[1], bh[2], bh[3], base + FK_KH + cc*8192 + swB);
                LDSM_X4(bl[0], bl[1], bl[2], bl[3], base + FK_KL + cc*8192 + swB);
                #pragma unroll
                for (int hv = 0; hv < 2; ++hv) {
                    MMA_BF16(s[ng*2+hv], ah, bh[2*hv], bh[2*hv+1]);
                    MMA_BF16(s[ng*2+hv], ah, bl[2*hv], bl[2*hv+1]);
                    MMA_BF16(s[ng*2+hv], al, bh[2*hv], bh[2*hv+1]);
                }
            }
        }
        __syncthreads();
        if (kt + 1 < 64) load_k_tile(base, Kh, Kl, (kt+1)*64, t);

        float mx0 = s[0][0], mx1 = s[0][2];
        #pragma unroll
        for (int nt = 0; nt < 8; ++nt) {
            mx0 = fmaxf(mx0, fmaxf(s[nt][0], s[nt][1]));
            mx1 = fmaxf(mx1, fmaxf(s[nt][2], s[nt][3]));
        }
        mx0 = fmaxf(mx0, __shfl_xor_sync(0xffffffffu, mx0, 1));
        mx0 = fmaxf(mx0, __shfl_xor_sync(0xffffffffu, mx0, 2));
        mx1 = fmaxf(mx1, __shfl_xor_sync(0xffffffffu, mx1, 1));
        mx1 = fmaxf(mx1, __shfl_xor_sync(0xffffffffu, mx1, 2));
        float mn0 = fmaxf(m0r, mx0), mn1 = fmaxf(m1r, mx1);
        float sc0 = __expf(m0r - mn0), sc1 = __expf(m1r - mn1);
        m0r = mn0; m1r = mn1;

        float sum0 = 0.f, sum1 = 0.f;
        #pragma unroll
        for (int nt = 0; nt < 8; ++nt) {
            s[nt][0] = __expf(s[nt][0] - mn0);
            s[nt][1] = __expf(s[nt][1] - mn0);
            s[nt][2] = __expf(s[nt][2] - mn1);
            s[nt][3] = __expf(s[nt][3] - mn1);
            sum0 += s[nt][0] + s[nt][1];
            sum1 += s[nt][2] + s[nt][3];
        }
        sum0 += __shfl_xor_sync(0xffffffffu, sum0, 1);
        sum0 += __shfl_xor_sync(0xffffffffu, sum0, 2);
        sum1 += __shfl_xor_sync(0xffffffffu, sum1, 1);
        sum1 += __shfl_xor_sync(0xffffffffu, sum1, 2);
        l0r = l0r * sc0 + sum0;
        l1r = l1r * sc1 + sum1;

        if (!__all_sync(0xffffffffu, (sc0 == 1.f) & (sc1 == 1.f))) {
            #pragma unroll
            for (int nb = 0; nb < 32; ++nb) {
                o[nb][0] *= sc0; o[nb][1] *= sc0;
                o[nb][2] *= sc1; o[nb][3] *= sc1;
            }
        }

        u32 af[4][4];
        #pragma unroll
        for (int ka = 0; ka < 4; ++ka) {
            af[ka][0] = h2u(s[2*ka][0],   s[2*ka][1]);
            af[ka][1] = h2u(s[2*ka][2],   s[2*ka][3]);
            af[ka][2] = h2u(s[2*ka+1][0], s[2*ka+1][1]);
            af[ka][3] = h2u(s[2*ka+1][2], s[2*ka+1][3]);
        }

        if (kt + 1 < 64) { CP_WAIT(1); } else { CP_WAIT(0); }
        __syncthreads();

        #pragma unroll
        for (int ka = 0; ka < 4; ++ka) {
            #pragma unroll
            for (int nb = 0; nb < 16; ++nb) {
                u32 swV = SW128((u32)((b_row + nb*16)*128 + (2*ka + b_ck)*16));
                u32 bf[4];
                LDSM_X4(bf[0], bf[1], bf[2], bf[3], base + FK_VT + swV);
                MMA_F16(o[nb*2],   af[ka], bf[0], bf[1]);
                MMA_F16(o[nb*2+1], af[ka], bf[2], bf[3]);
            }
        }
        __syncthreads();
    }

    float i0 = 1.f / l0r, i1 = 1.f / l1r;
    int row0 = m0 + wid*16 + (lane >> 2);
    float* O0 = out + ((size_t)b*Sn + row0) * En;
    #pragma unroll
    for (int nb = 0; nb < 32; ++nb) {
        int c = nb*8 + (lane & 3)*2;
        float2 v0, v1;
        v0.x = 1.f / (1.f + __expf(-o[nb][0] * i0));
        v0.y = 1.f / (1.f + __expf(-o[nb][1] * i0));
        v1.x = 1.f / (1.f + __expf(-o[nb][2] * i1));
        v1.y = 1.f / (1.f + __expf(-o[nb][3] * i1));
        *(float2*)&O0[c]          = v0;
        *(float2*)&O0[8*En + c]   = v1;
    }
}

// ==================================================================
// Launch
// ==================================================================
extern "C" void kernel_launch(void* const* d_in, const int* in_sizes, int n_in,
                              void* d_out, int out_size)
{
    const float* x  = (const float*)d_in[0];
    const float* Wq = (const float*)d_in[1];
    const float* bq = (const float*)d_in[2];
    const float* Wk = (const float*)d_in[3];
    const float* bk = (const float*)d_in[4];
    const float* Wv = (const float*)d_in[5];
    const float* bv = (const float*)d_in[6];
    float* out = (float*)d_out;

    cudaFuncSetAttribute(qkv_mma_kernel,
        cudaFuncAttributeMaxDynamicSharedMemorySize, SMEM_GEMM);
    cudaFuncSetAttribute(flash_kernel,
        cudaFuncAttributeMaxDynamicSharedMemorySize, SMEM_FK);

    split_x_kernel<<<Mtot * Cn / 1024, 256>>>(x);
    prep_w_kernel<<<dim3(8, 8, 3), dim3(32, 8)>>>(Wq, Wk, Wv);
    qkv_mma_kernel<<<dim3(128, 3), 256, SMEM_GEMM>>>(bq, bk, bv);
    flash_kernel<<<dim3(32, 4), 256, SMEM_FK>>>(out);
}

// round 8
// speedup vs baseline: 2.7073x; 1.1958x over previous
#include <cuda_runtime.h>
#include <cuda_bf16.h>
#include <cuda_fp16.h>
#include <math.h>
#include <stdint.h>

#define Bn 4
#define Sn 4096
#define Cn 256
#define En 256
#define Mtot (Bn * Sn)

typedef unsigned int u32;
typedef unsigned long long u64;

// ------------------------------------------------------------------
// Static device scratch (no allocation allowed)
// ------------------------------------------------------------------
__device__ __nv_bfloat16 g_xh[Mtot * Cn];
__device__ __nv_bfloat16 g_xl[Mtot * Cn];
__device__ __nv_bfloat16 g_Wth[3 * Cn * Cn];   // Wt[which][n][k]
__device__ __nv_bfloat16 g_Wtl[3 * Cn * Cn];
__device__ __half g_Qf[Mtot * Cn];             // Q fp16 single plane
__device__ __half g_KfH[Mtot * Cn];            // K fp16 hi
__device__ __half g_KfL[Mtot * Cn];            // K fp16 lo (residual)
__device__ __half g_Vt[Bn * En * Sn];          // V transposed fp16: [b][e][s]

// ------------------------------------------------------------------
// helpers
// ------------------------------------------------------------------
__device__ __forceinline__ u32 smem_u32(const void* p) {
    u32 a;
    asm("{ .reg .u64 t; cvta.to.shared.u64 t, %1; cvt.u32.u64 %0, t; }"
        : "=r"(a) : "l"(p));
    return a;
}
#define SW128(o) ((o) ^ (((o) >> 3) & 0x70))

__device__ __forceinline__ void cp16(u32 dst, const void* src) {
    asm volatile("cp.async.cg.shared.global [%0], [%1], 16;" :: "r"(dst), "l"(src));
}
#define CP_COMMIT() asm volatile("cp.async.commit_group;" ::: "memory")
#define CP_WAIT(n)  asm volatile("cp.async.wait_group %0;" :: "n"(n) : "memory")

#define LDSM_X4(r0, r1, r2, r3, addr)                                        \
    asm volatile("ldmatrix.sync.aligned.m8n8.x4.shared.b16 {%0,%1,%2,%3}, [%4];" \
                 : "=r"(r0), "=r"(r1), "=r"(r2), "=r"(r3) : "r"(addr))

#define MMA_BF16(d, a, b0, b1)                                               \
    asm volatile("mma.sync.aligned.m16n8k16.row.col.f32.bf16.bf16.f32 "      \
                 "{%0,%1,%2,%3}, {%4,%5,%6,%7}, {%8,%9}, {%0,%1,%2,%3};"     \
                 : "+f"((d)[0]), "+f"((d)[1]), "+f"((d)[2]), "+f"((d)[3])    \
                 : "r"((a)[0]), "r"((a)[1]), "r"((a)[2]), "r"((a)[3]),       \
                   "r"(b0), "r"(b1))

#define MMA_F16(d, a, b0, b1)                                                \
    asm volatile("mma.sync.aligned.m16n8k16.row.col.f32.f16.f16.f32 "        \
                 "{%0,%1,%2,%3}, {%4,%5,%6,%7}, {%8,%9}, {%0,%1,%2,%3};"     \
                 : "+f"((d)[0]), "+f"((d)[1]), "+f"((d)[2]), "+f"((d)[3])    \
                 : "r"((a)[0]), "r"((a)[1]), "r"((a)[2]), "r"((a)[3]),       \
                   "r"(b0), "r"(b1))

__device__ __forceinline__ u32 h2u(float a, float b) {
    __half2 h = __floats2half2_rn(a, b);
    return *(u32*)&h;
}

// ==================================================================
// Kernel P1: split x into bf16 hi/lo planes
// ==================================================================
__global__ __launch_bounds__(256)
void split_x_kernel(const float* __restrict__ x)
{
    size_t i = ((size_t)blockIdx.x * 256 + threadIdx.x) * 4;
    float4 v = *(const float4*)&x[i];
    float a[4] = {v.x, v.y, v.z, v.w};
    union { __nv_bfloat16 h[4]; uint2 q; } H, L;
    #pragma unroll
    for (int j = 0; j < 4; ++j) {
        H.h[j] = __float2bfloat16(a[j]);
        L.h[j] = __float2bfloat16(a[j] - __bfloat162float(H.h[j]));
    }
    *(uint2*)&g_xh[i] = H.q;
    *(uint2*)&g_xl[i] = L.q;
}

// ==================================================================
// Kernel P2: transpose + split W -> Wt[which][n][k] bf16 hi/lo
// ==================================================================
__global__ __launch_bounds__(256)
void prep_w_kernel(const float* __restrict__ Wq,
                   const float* __restrict__ Wk,
                   const float* __restrict__ Wv)
{
    __shared__ float tile[32][33];
    int which = blockIdx.z;
    const float* W = (which == 0) ? Wq : (which == 1) ? Wk : Wv;
    int k0 = blockIdx.x * 32, n0 = blockIdx.y * 32;
    int tx = threadIdx.x, ty = threadIdx.y;

    #pragma unroll
    for (int j = ty; j < 32; j += 8)
        tile[j][tx] = W[(size_t)(k0 + j) * Cn + n0 + tx];
    __syncthreads();
    #pragma unroll
    for (int j = ty; j < 32; j += 8) {
        float v = tile[tx][j];     // = W[k0+tx][n0+j]
        __nv_bfloat16 hi = __float2bfloat16(v);
        __nv_bfloat16 lo = __float2bfloat16(v - __bfloat162float(hi));
        size_t o = (size_t)which * Cn * Cn + (size_t)(n0 + j) * Cn + k0 + tx;
        g_Wth[o] = hi;
        g_Wtl[o] = lo;
    }
}

// ==================================================================
// Kernel P3: QKV projection GEMM (bf16 3-term mma).
// Epilogues: Q -> fp16 single plane; K -> fp16 hi/lo planes;
// V -> fp16 transposed into g_Vt.
// ==================================================================
#define OFF_AH 0
#define OFF_AL (16*1024)
#define OFF_BH (32*1024)
#define OFF_BL (64*1024)
#define CHUNK_BYTES (96*1024)
#define SMEM_GEMM (2*CHUNK_BYTES + 1024)

__device__ __forceinline__ void load_chunk(u32 buf,
    const __nv_bfloat16* Ah, const __nv_bfloat16* Al,
    const __nv_bfloat16* Bh, const __nv_bfloat16* Bl,
    int c0, int t)
{
    #pragma unroll
    for (int j = 0; j < 4; ++j) {
        int idx = t + 256 * j; int row = idx >> 3, g = idx & 7;
        cp16(buf + OFF_AH + SW128(row*128 + g*16), Ah + (size_t)row*Cn + c0 + g*8);
    }
    #pragma unroll
    for (int j = 0; j < 4; ++j) {
        int idx = t + 256 * j; int row = idx >> 3, g = idx & 7;
        cp16(buf + OFF_AL + SW128(row*128 + g*16), Al + (size_t)row*Cn + c0 + g*8);
    }
    #pragma unroll
    for (int j = 0; j < 8; ++j) {
        int idx = t + 256 * j; int row = idx >> 3, g = idx & 7;
        cp16(buf + OFF_BH + SW128(row*128 + g*16), Bh + (size_t)row*Cn + c0 + g*8);
    }
    #pragma unroll
    for (int j = 0; j < 8; ++j) {
        int idx = t + 256 * j; int row = idx >> 3, g = idx & 7;
        cp16(buf + OFF_BL + SW128(row*128 + g*16), Bl + (size_t)row*Cn + c0 + g*8);
    }
    CP_COMMIT();
}

__global__ __launch_bounds__(256, 1)
void qkv_mma_kernel(const float* __restrict__ bq,
                    const float* __restrict__ bk,
                    const float* __restrict__ bv)
{
    extern __shared__ __align__(1024) char dsm[];
    u32 sb0  = smem_u32(dsm);
    u32 base = (sb0 + 1023) & ~1023u;
    char* alig = dsm + (base - sb0);
    int t = threadIdx.x, wid = t >> 5, lane = t & 31;
    int warp_m = wid & 1, warp_n = wid >> 1;

    int m0 = blockIdx.x * 128;
    int which = blockIdx.y;
    const float* bias = (which == 0) ? bq : (which == 1) ? bk : bv;

    const __nv_bfloat16* Ah = g_xh + (size_t)m0 * Cn;
    const __nv_bfloat16* Al = g_xl + (size_t)m0 * Cn;
    const __nv_bfloat16* Bh = g_Wth + (size_t)which * Cn * Cn;
    const __nv_bfloat16* Bl = g_Wtl + (size_t)which * Cn * Cn;

    float acc[4][8][4];
    #pragma unroll
    for (int i = 0; i < 4; ++i)
        #pragma unroll
        for (int j = 0; j < 8; ++j)
            #pragma unroll
            for (int k = 0; k < 4; ++k) acc[i][j][k] = 0.f;

    int a_row = warp_m*64 + (lane & 15);
    int a_ck  = (lane >> 4) & 1;
    int b_row = warp_n*64 + (lane & 7) + ((lane >> 4) << 3);
    int b_ck  = (lane >> 3) & 1;

    load_chunk(base, Ah, Al, Bh, Bl, 0, t);

    for (int kc = 0; kc < 4; ++kc) {
        if (kc + 1 < 4) {
            load_chunk(base + ((kc+1)&1)*CHUNK_BYTES, Ah, Al, Bh, Bl, (kc+1)*64, t);
            asm volatile("cp.async.wait_group 1;" ::: "memory");
        } else {
            asm volatile("cp.async.wait_group 0;" ::: "memory");
        }
        __syncthreads();

        u32 buf = base + (kc & 1) * CHUNK_BYTES;
        #pragma unroll
        for (int ks = 0; ks < 4; ++ks) {
            u32 ah[4][4], al[4][4];
            #pragma unroll
            for (int mt = 0; mt < 4; ++mt) {
                int off = (a_row + mt*16)*128 + (2*ks + a_ck)*16;
                u32 sw = SW128(off);
                LDSM_X4(ah[mt][0], ah[mt][1], ah[mt][2], ah[mt][3], buf + OFF_AH + sw);
                LDSM_X4(al[mt][0], al[mt][1], al[mt][2], al[mt][3], buf + OFF_AL + sw);
            }
            #pragma unroll
            for (int np = 0; np < 4; ++np) {
                int off = (b_row + np*16)*128 + (2*ks + b_ck)*16;
                u32 sw = SW128(off);
                u32 bh[4], bl[4];
                LDSM_X4(bh[0], bh[1], bh[2], bh[3], buf + OFF_BH + sw);
                LDSM_X4(bl[0], bl[1], bl[2], bl[3], buf + OFF_BL + sw);
                #pragma unroll
                for (int mt = 0; mt < 4; ++mt) {
                    #pragma unroll
                    for (int j = 0; j < 2; ++j) {
                        MMA_BF16(acc[mt][np*2+j], ah[mt], bh[2*j], bh[2*j+1]);
                        MMA_BF16(acc[mt][np*2+j], ah[mt], bl[2*j], bl[2*j+1]);
                        MMA_BF16(acc[mt][np*2+j], al[mt], bh[2*j], bh[2*j+1]);
                    }
                }
            }
        }
        __syncthreads();
    }

    // ---- epilogue ----
    int rg = warp_m*64 + (lane >> 2);
    int cg = warp_n*64 + (lane & 3) * 2;

    if (which == 0) {
        // Q: fp16 single plane
        #pragma unroll
        for (int mt = 0; mt < 4; ++mt) {
            #pragma unroll
            for (int nt = 0; nt < 8; ++nt) {
                int r = rg + mt*16, c = cg + nt*8;
                float b0 = bias[c], b1 = bias[c+1];
                #pragma unroll
                for (int hv = 0; hv < 2; ++hv) {
                    int rr = r + hv*8;
                    float v0 = acc[mt][nt][hv*2]   + b0;
                    float v1 = acc[mt][nt][hv*2+1] + b1;
                    *(u32*)&g_Qf[(size_t)(m0 + rr) * Cn + c] = h2u(v0, v1);
                }
            }
        }
    } else if (which == 1) {
        // K: fp16 hi/lo planes
        #pragma unroll
        for (int mt = 0; mt < 4; ++mt) {
            #pragma unroll
            for (int nt = 0; nt < 8; ++nt) {
                int r = rg + mt*16, c = cg + nt*8;
                float b0 = bias[c], b1 = bias[c+1];
                #pragma unroll
                for (int hv = 0; hv < 2; ++hv) {
                    int rr = r + hv*8;
                    float v0 = acc[mt][nt][hv*2]   + b0;
                    float v1 = acc[mt][nt][hv*2+1] + b1;
                    __half h0 = __float2half_rn(v0);
                    __half h1 = __float2half_rn(v1);
                    __half l0 = __float2half_rn(v0 - __half2float(h0));
                    __half l1 = __float2half_rn(v1 - __half2float(h1));
                    size_t idx = (size_t)(m0 + rr) * Cn + c;
                    union { __half h[2]; u32 q; } P0, P1;
                    P0.h[0] = h0; P0.h[1] = h1;
                    P1.h[0] = l0; P1.h[1] = l1;
                    *(u32*)&g_KfH[idx] = P0.q;
                    *(u32*)&g_KfL[idx] = P1.q;
                }
            }
        }
    } else {
        // V: stage fp16 transposed [e][s] then coalesced write to g_Vt
        __half* stage = (__half*)alig;       // [256 e][136 pad]
        #pragma unroll
        for (int mt = 0; mt < 4; ++mt) {
            #pragma unroll
            for (int nt = 0; nt < 8; ++nt) {
                int r = rg + mt*16, c = cg + nt*8;
                float b0 = bias[c], b1 = bias[c+1];
                #pragma unroll
                for (int hv = 0; hv < 2; ++hv) {
                    int rr = r + hv*8;
                    stage[(c)   * 136 + rr] = __float2half_rn(acc[mt][nt][hv*2]   + b0);
                    stage[(c+1) * 136 + rr] = __float2half_rn(acc[mt][nt][hv*2+1] + b1);
                }
            }
        }
        __syncthreads();
        int b = m0 >> 12, s0 = m0 & 4095;
        #pragma unroll
        for (int i = t; i < 256 * 32; i += 256) {
            int e = i >> 5, sseg = i & 31;
            uint2 v;
            v.x = *(u32*)&stage[e*136 + sseg*4];
            v.y = *(u32*)&stage[e*136 + sseg*4 + 2];
            *(uint2*)&g_Vt[((size_t)(b * En + e)) * Sn + s0 + sseg*4] = v;
        }
    }
}

// ==================================================================
// Kernel 3: fused flash attention + sigmoid.
// Q fp16 single (64KB resident), K fp16 hi/lo (64KB single buffer),
// V fp16 double-buffered (2 x 32KB). 2-term QK, 1-term PV.
// smem total 192KB. 3 syncs/tile.
// ==================================================================
#define FK_Q  0
#define FK_KH (64*1024)
#define FK_KL (96*1024)
#define FK_V0 (128*1024)
#define SMEM_FK (192*1024 + 1024)

__device__ __forceinline__ void load_k_tile(u32 base,
    const __half* Kh, const __half* Kl, int s0, int t)
{
    #pragma unroll
    for (int j = 0; j < 8; ++j) {
        int idx = t + 256*j;
        int cc = idx >> 9, rr = (idx >> 3) & 63, g = idx & 7;
        cp16(base + FK_KH + cc*8192 + SW128(rr*128 + g*16),
             Kh + (size_t)(s0 + rr)*Cn + cc*64 + g*8);
    }
    #pragma unroll
    for (int j = 0; j < 8; ++j) {
        int idx = t + 256*j;
        int cc = idx >> 9, rr = (idx >> 3) & 63, g = idx & 7;
        cp16(base + FK_KL + cc*8192 + SW128(rr*128 + g*16),
             Kl + (size_t)(s0 + rr)*Cn + cc*64 + g*8);
    }
    CP_COMMIT();
}

__device__ __forceinline__ void load_v_tile(u32 base, int vb,
    const __half* Vt, int s0, int t)
{
    #pragma unroll
    for (int j = 0; j < 8; ++j) {
        int idx = t + 256*j;
        int rr = idx >> 3, g = idx & 7;
        cp16(base + FK_V0 + vb*32768 + SW128(rr*128 + g*16),
             Vt + (size_t)rr*Sn + s0 + g*8);
    }
    CP_COMMIT();
}

__global__ __launch_bounds__(256, 1)
void flash_kernel(float* __restrict__ out)
{
    extern __shared__ __align__(1024) char dsm[];
    u32 sb0 = smem_u32(dsm);
    u32 base = (sb0 + 1023) & ~1023u;
    int t = threadIdx.x, wid = t >> 5, lane = t & 31;
    int b = blockIdx.y, m0 = blockIdx.x * 128;

    const __half* Qf = g_Qf + ((size_t)(b*Sn + m0))*Cn;
    const __half* Kh = g_KfH + (size_t)b*Sn*Cn;
    const __half* Kl = g_KfL + (size_t)b*Sn*Cn;
    const __half* Vt = g_Vt + (size_t)b*En*Sn;

    // prologue: Q (G1), K0 (G2), V0 (G3)
    #pragma unroll
    for (int j = 0; j < 16; ++j) {
        int idx = t + 256*j;
        int cc = idx >> 10, rr = (idx >> 3) & 127, g = idx & 7;
        cp16(base + FK_Q + cc*16384 + SW128(rr*128 + g*16),
             Qf + (size_t)rr*Cn + cc*64 + g*8);
    }
    CP_COMMIT();
    load_k_tile(base, Kh, Kl, 0, t);
    load_v_tile(base, 0, Vt, 0, t);

    float o[32][4];
    #pragma unroll
    for (int i = 0; i < 32; ++i)
        #pragma unroll
        for (int j = 0; j < 4; ++j) o[i][j] = 0.f;
    float m0r = -INFINITY, m1r = -INFINITY, l0r = 0.f, l1r = 0.f;

    int a_row = wid*16 + (lane & 15);
    int a_ck  = (lane >> 4) & 1;
    int b_row = (lane & 7) + ((lane >> 4) << 3);
    int b_ck  = (lane >> 3) & 1;

    for (int kt = 0; kt < 64; ++kt) {
        CP_WAIT(1);                        // K(kt) ready (older than V(kt))
        __syncthreads();

        // ---- QK: 2-term fp16 (Q single x K hi/lo) ----
        float s[8][4];
        #pragma unroll
        for (int i = 0; i < 8; ++i)
            #pragma unroll
            for (int j = 0; j < 4; ++j) s[i][j] = 0.f;

        #pragma unroll
        for (int ks = 0; ks < 16; ++ks) {
            int cc = ks >> 2, kl2 = ks & 3;
            u32 swA = SW128((u32)(a_row*128 + (2*kl2 + a_ck)*16));
            u32 aq[4];
            LDSM_X4(aq[0], aq[1], aq[2], aq[3], base + FK_Q + cc*16384 + swA);
            #pragma unroll
            for (int ng = 0; ng < 4; ++ng) {
                u32 swB = SW128((u32)((b_row + ng*16)*128 + (2*kl2 + b_ck)*16));
                u32 bh[4], bl[4];
                LDSM_X4(bh[0], bh[1], bh[2], bh[3], base + FK_KH + cc*8192 + swB);
                LDSM_X4(bl[0], bl[1], bl[2], bl[3], base + FK_KL + cc*8192 + swB);
                #pragma unroll
                for (int hv = 0; hv < 2; ++hv) {
                    MMA_F16(s[ng*2+hv], aq, bh[2*hv], bh[2*hv+1]);
                    MMA_F16(s[ng*2+hv], aq, bl[2*hv], bl[2*hv+1]);
                }
            }
        }
        __syncthreads();                   // K tile consumed by all warps
        if (kt + 1 < 64) {
            load_k_tile(base, Kh, Kl, (kt+1)*64, t);          // group K(kt+1)
            load_v_tile(base, (kt+1)&1, Vt, (kt+1)*64, t);    // group V(kt+1)
        }

        // ---- online softmax on 2 owned rows ----
        float mx0 = s[0][0], mx1 = s[0][2];
        #pragma unroll
        for (int nt = 0; nt < 8; ++nt) {
            mx0 = fmaxf(mx0, fmaxf(s[nt][0], s[nt][1]));
            mx1 = fmaxf(mx1, fmaxf(s[nt][2], s[nt][3]));
        }
        mx0 = fmaxf(mx0, __shfl_xor_sync(0xffffffffu, mx0, 1));
        mx0 = fmaxf(mx0, __shfl_xor_sync(0xffffffffu, mx0, 2));
        mx1 = fmaxf(mx1, __shfl_xor_sync(0xffffffffu, mx1, 1));
        mx1 = fmaxf(mx1, __shfl_xor_sync(0xffffffffu, mx1, 2));
        float mn0 = fmaxf(m0r, mx0), mn1 = fmaxf(m1r, mx1);
        float sc0 = __expf(m0r - mn0), sc1 = __expf(m1r - mn1);
        m0r = mn0; m1r = mn1;

        float sum0 = 0.f, sum1 = 0.f;
        #pragma unroll
        for (int nt = 0; nt < 8; ++nt) {
            s[nt][0] = __expf(s[nt][0] - mn0);
            s[nt][1] = __expf(s[nt][1] - mn0);
            s[nt][2] = __expf(s[nt][2] - mn1);
            s[nt][3] = __expf(s[nt][3] - mn1);
            sum0 += s[nt][0] + s[nt][1];
            sum1 += s[nt][2] + s[nt][3];
        }
        sum0 += __shfl_xor_sync(0xffffffffu, sum0, 1);
        sum0 += __shfl_xor_sync(0xffffffffu, sum0, 2);
        sum1 += __shfl_xor_sync(0xffffffffu, sum1, 1);
        sum1 += __shfl_xor_sync(0xffffffffu, sum1, 2);
        l0r = l0r * sc0 + sum0;
        l1r = l1r * sc1 + sum1;

        if (!__all_sync(0xffffffffu, (sc0 == 1.f) & (sc1 == 1.f))) {
            #pragma unroll
            for (int nb = 0; nb < 32; ++nb) {
                o[nb][0] *= sc0; o[nb][1] *= sc0;
                o[nb][2] *= sc1; o[nb][3] *= sc1;
            }
        }

        // ---- pack P (C-frag -> A-frag, fp16) ----
        u32 af[4][4];
        #pragma unroll
        for (int ka = 0; ka < 4; ++ka) {
            af[ka][0] = h2u(s[2*ka][0],   s[2*ka][1]);
            af[ka][1] = h2u(s[2*ka][2],   s[2*ka][3]);
            af[ka][2] = h2u(s[2*ka+1][0], s[2*ka+1][1]);
            af[ka][3] = h2u(s[2*ka+1][2], s[2*ka+1][3]);
        }

        // V(kt) ready: pending groups are K(kt+1), V(kt+1)
        if (kt + 1 < 64) { CP_WAIT(2); } else { CP_WAIT(0); }
        __syncthreads();

        // ---- PV ----
        u32 vbase = base + FK_V0 + (kt & 1)*32768;
        #pragma unroll
        for (int ka = 0; ka < 4; ++ka) {
            #pragma unroll
            for (int nb = 0; nb < 16; ++nb) {
                u32 swV = SW128((u32)((b_row + nb*16)*128 + (2*ka + b_ck)*16));
                u32 bf[4];
                LDSM_X4(bf[0], bf[1], bf[2], bf[3], vbase + swV);
                MMA_F16(o[nb*2],   af[ka], bf[0], bf[1]);
                MMA_F16(o[nb*2+1], af[ka], bf[2], bf[3]);
            }
        }
        // no post-PV sync: V is double-buffered; K(kt+1) overwrite was
        // already fenced by the post-QK sync above.
    }

    float i0 = 1.f / l0r, i1 = 1.f / l1r;
    int row0 = m0 + wid*16 + (lane >> 2);
    float* O0 = out + ((size_t)b*Sn + row0) * En;
    #pragma unroll
    for (int nb = 0; nb < 32; ++nb) {
        int c = nb*8 + (lane & 3)*2;
        float2 v0, v1;
        v0.x = 1.f / (1.f + __expf(-o[nb][0] * i0));
        v0.y = 1.f / (1.f + __expf(-o[nb][1] * i0));
        v1.x = 1.f / (1.f + __expf(-o[nb][2] * i1));
        v1.y = 1.f / (1.f + __expf(-o[nb][3] * i1));
        *(float2*)&O0[c]          = v0;
        *(float2*)&O0[8*En + c]   = v1;
    }
}

// ==================================================================
// Launch
// ==================================================================
extern "C" void kernel_launch(void* const* d_in, const int* in_sizes, int n_in,
                              void* d_out, int out_size)
{
    const float* x  = (const float*)d_in[0];
    const float* Wq = (const float*)d_in[1];
    const float* bq = (const float*)d_in[2];
    const float* Wk = (const float*)d_in[3];
    const float* bk = (const float*)d_in[4];
    const float* Wv = (const float*)d_in[5];
    const float* bv = (const float*)d_in[6];
    float* out = (float*)d_out;

    cudaFuncSetAttribute(qkv_mma_kernel,
        cudaFuncAttributeMaxDynamicSharedMemorySize, SMEM_GEMM);
    cudaFuncSetAttribute(flash_kernel,
        cudaFuncAttributeMaxDynamicSharedMemorySize, SMEM_FK);

    split_x_kernel<<<Mtot * Cn / 1024, 256>>>(x);
    prep_w_kernel<<<dim3(8, 8, 3), dim3(32, 8)>>>(Wq, Wk, Wv);
    qkv_mma_kernel<<<dim3(128, 3), 256, SMEM_GEMM>>>(bq, bk, bv);
    flash_kernel<<<dim3(32, 4), 256, SMEM_FK>>>(out);
}

// round 9
// speedup vs baseline: 3.6609x; 1.3522x over previous
#include <cuda_runtime.h>
#include <cuda_bf16.h>
#include <cuda_fp16.h>
#include <math.h>
#include <stdint.h>

#define Bn 4
#define Sn 4096
#define Cn 256
#define En 256
#define Mtot (Bn * Sn)

typedef unsigned int u32;
typedef unsigned long long u64;

// ------------------------------------------------------------------
// Static device scratch (no allocation allowed)
// ------------------------------------------------------------------
__device__ __nv_bfloat16 g_xh[Mtot * Cn];
__device__ __nv_bfloat16 g_xl[Mtot * Cn];
__device__ __nv_bfloat16 g_Wth[3 * Cn * Cn];   // Wt[which][n][k]
__device__ __nv_bfloat16 g_Wtl[3 * Cn * Cn];
__device__ __half g_Qf[Mtot * Cn];             // Q fp16
__device__ __half g_Kf[Mtot * Cn];             // K fp16
__device__ __half g_Vt[Bn * En * Sn];          // V transposed fp16: [b][e][s]

// ------------------------------------------------------------------
// helpers
// ------------------------------------------------------------------
__device__ __forceinline__ u32 smem_u32(const void* p) {
    u32 a;
    asm("{ .reg .u64 t; cvta.to.shared.u64 t, %1; cvt.u32.u64 %0, t; }"
        : "=r"(a) : "l"(p));
    return a;
}
#define SW128(o) ((o) ^ (((o) >> 3) & 0x70))

__device__ __forceinline__ void cp16(u32 dst, const void* src) {
    asm volatile("cp.async.cg.shared.global [%0], [%1], 16;" :: "r"(dst), "l"(src));
}
#define CP_COMMIT() asm volatile("cp.async.commit_group;" ::: "memory")
#define CP_WAIT(n)  asm volatile("cp.async.wait_group %0;" :: "n"(n) : "memory")

#define LDSM_X4(r0, r1, r2, r3, addr)                                        \
    asm volatile("ldmatrix.sync.aligned.m8n8.x4.shared.b16 {%0,%1,%2,%3}, [%4];" \
                 : "=r"(r0), "=r"(r1), "=r"(r2), "=r"(r3) : "r"(addr))

#define MMA_BF16(d, a, b0, b1)                                               \
    asm volatile("mma.sync.aligned.m16n8k16.row.col.f32.bf16.bf16.f32 "      \
                 "{%0,%1,%2,%3}, {%4,%5,%6,%7}, {%8,%9}, {%0,%1,%2,%3};"     \
                 : "+f"((d)[0]), "+f"((d)[1]), "+f"((d)[2]), "+f"((d)[3])    \
                 : "r"((a)[0]), "r"((a)[1]), "r"((a)[2]), "r"((a)[3]),       \
                   "r"(b0), "r"(b1))

#define MMA_F16(d, a, b0, b1)                                                \
    asm volatile("mma.sync.aligned.m16n8k16.row.col.f32.f16.f16.f32 "        \
                 "{%0,%1,%2,%3}, {%4,%5,%6,%7}, {%8,%9}, {%0,%1,%2,%3};"     \
                 : "+f"((d)[0]), "+f"((d)[1]), "+f"((d)[2]), "+f"((d)[3])    \
                 : "r"((a)[0]), "r"((a)[1]), "r"((a)[2]), "r"((a)[3]),       \
                   "r"(b0), "r"(b1))

__device__ __forceinline__ u32 h2u(float a, float b) {
    __half2 h = __floats2half2_rn(a, b);
    return *(u32*)&h;
}

// ==================================================================
// Kernel P1: split x into bf16 hi/lo planes
// ==================================================================
__global__ __launch_bounds__(256)
void split_x_kernel(const float* __restrict__ x)
{
    size_t i = ((size_t)blockIdx.x * 256 + threadIdx.x) * 4;
    float4 v = *(const float4*)&x[i];
    float a[4] = {v.x, v.y, v.z, v.w};
    union { __nv_bfloat16 h[4]; uint2 q; } H, L;
    #pragma unroll
    for (int j = 0; j < 4; ++j) {
        H.h[j] = __float2bfloat16(a[j]);
        L.h[j] = __float2bfloat16(a[j] - __bfloat162float(H.h[j]));
    }
    *(uint2*)&g_xh[i] = H.q;
    *(uint2*)&g_xl[i] = L.q;
}

// ==================================================================
// Kernel P2: transpose + split W -> Wt[which][n][k] bf16 hi/lo
// ==================================================================
__global__ __launch_bounds__(256)
void prep_w_kernel(const float* __restrict__ Wq,
                   const float* __restrict__ Wk,
                   const float* __restrict__ Wv)
{
    __shared__ float tile[32][33];
    int which = blockIdx.z;
    const float* W = (which == 0) ? Wq : (which == 1) ? Wk : Wv;
    int k0 = blockIdx.x * 32, n0 = blockIdx.y * 32;
    int tx = threadIdx.x, ty = threadIdx.y;

    #pragma unroll
    for (int j = ty; j < 32; j += 8)
        tile[j][tx] = W[(size_t)(k0 + j) * Cn + n0 + tx];
    __syncthreads();
    #pragma unroll
    for (int j = ty; j < 32; j += 8) {
        float v = tile[tx][j];     // = W[k0+tx][n0+j]
        __nv_bfloat16 hi = __float2bfloat16(v);
        __nv_bfloat16 lo = __float2bfloat16(v - __bfloat162float(hi));
        size_t o = (size_t)which * Cn * Cn + (size_t)(n0 + j) * Cn + k0 + tx;
        g_Wth[o] = hi;
        g_Wtl[o] = lo;
    }
}

// ==================================================================
// Kernel P3: QKV projection GEMM (bf16 3-term mma).
// Epilogues: Q/K -> fp16 planes; V -> fp16 transposed into g_Vt.
// ==================================================================
#define OFF_AH 0
#define OFF_AL (16*1024)
#define OFF_BH (32*1024)
#define OFF_BL (64*1024)
#define CHUNK_BYTES (96*1024)
#define SMEM_GEMM (2*CHUNK_BYTES + 1024)

__device__ __forceinline__ void load_chunk(u32 buf,
    const __nv_bfloat16* Ah, const __nv_bfloat16* Al,
    const __nv_bfloat16* Bh, const __nv_bfloat16* Bl,
    int c0, int t)
{
    #pragma unroll
    for (int j = 0; j < 4; ++j) {
        int idx = t + 256 * j; int row = idx >> 3, g = idx & 7;
        cp16(buf + OFF_AH + SW128(row*128 + g*16), Ah + (size_t)row*Cn + c0 + g*8);
    }
    #pragma unroll
    for (int j = 0; j < 4; ++j) {
        int idx = t + 256 * j; int row = idx >> 3, g = idx & 7;
        cp16(buf + OFF_AL + SW128(row*128 + g*16), Al + (size_t)row*Cn + c0 + g*8);
    }
    #pragma unroll
    for (int j = 0; j < 8; ++j) {
        int idx = t + 256 * j; int row = idx >> 3, g = idx & 7;
        cp16(buf + OFF_BH + SW128(row*128 + g*16), Bh + (size_t)row*Cn + c0 + g*8);
    }
    #pragma unroll
    for (int j = 0; j < 8; ++j) {
        int idx = t + 256 * j; int row = idx >> 3, g = idx & 7;
        cp16(buf + OFF_BL + SW128(row*128 + g*16), Bl + (size_t)row*Cn + c0 + g*8);
    }
    CP_COMMIT();
}

__global__ __launch_bounds__(256, 1)
void qkv_mma_kernel(const float* __restrict__ bq,
                    const float* __restrict__ bk,
                    const float* __restrict__ bv)
{
    extern __shared__ __align__(1024) char dsm[];
    u32 sb0  = smem_u32(dsm);
    u32 base = (sb0 + 1023) & ~1023u;
    char* alig = dsm + (base - sb0);
    int t = threadIdx.x, wid = t >> 5, lane = t & 31;
    int warp_m = wid & 1, warp_n = wid >> 1;

    int m0 = blockIdx.x * 128;
    int which = blockIdx.y;
    const float* bias = (which == 0) ? bq : (which == 1) ? bk : bv;

    const __nv_bfloat16* Ah = g_xh + (size_t)m0 * Cn;
    const __nv_bfloat16* Al = g_xl + (size_t)m0 * Cn;
    const __nv_bfloat16* Bh = g_Wth + (size_t)which * Cn * Cn;
    const __nv_bfloat16* Bl = g_Wtl + (size_t)which * Cn * Cn;

    float acc[4][8][4];
    #pragma unroll
    for (int i = 0; i < 4; ++i)
        #pragma unroll
        for (int j = 0; j < 8; ++j)
            #pragma unroll
            for (int k = 0; k < 4; ++k) acc[i][j][k] = 0.f;

    int a_row = warp_m*64 + (lane & 15);
    int a_ck  = (lane >> 4) & 1;
    int b_row = warp_n*64 + (lane & 7) + ((lane >> 4) << 3);
    int b_ck  = (lane >> 3) & 1;

    load_chunk(base, Ah, Al, Bh, Bl, 0, t);

    for (int kc = 0; kc < 4; ++kc) {
        if (kc + 1 < 4) {
            load_chunk(base + ((kc+1)&1)*CHUNK_BYTES, Ah, Al, Bh, Bl, (kc+1)*64, t);
            asm volatile("cp.async.wait_group 1;" ::: "memory");
        } else {
            asm volatile("cp.async.wait_group 0;" ::: "memory");
        }
        __syncthreads();

        u32 buf = base + (kc & 1) * CHUNK_BYTES;
        #pragma unroll
        for (int ks = 0; ks < 4; ++ks) {
            u32 ah[4][4], al[4][4];
            #pragma unroll
            for (int mt = 0; mt < 4; ++mt) {
                int off = (a_row + mt*16)*128 + (2*ks + a_ck)*16;
                u32 sw = SW128(off);
                LDSM_X4(ah[mt][0], ah[mt][1], ah[mt][2], ah[mt][3], buf + OFF_AH + sw);
                LDSM_X4(al[mt][0], al[mt][1], al[mt][2], al[mt][3], buf + OFF_AL + sw);
            }
            #pragma unroll
            for (int np = 0; np < 4; ++np) {
                int off = (b_row + np*16)*128 + (2*ks + b_ck)*16;
                u32 sw = SW128(off);
                u32 bh[4], bl[4];
                LDSM_X4(bh[0], bh[1], bh[2], bh[3], buf + OFF_BH + sw);
                LDSM_X4(bl[0], bl[1], bl[2], bl[3], buf + OFF_BL + sw);
                #pragma unroll
                for (int mt = 0; mt < 4; ++mt) {
                    #pragma unroll
                    for (int j = 0; j < 2; ++j) {
                        MMA_BF16(acc[mt][np*2+j], ah[mt], bh[2*j], bh[2*j+1]);
                        MMA_BF16(acc[mt][np*2+j], ah[mt], bl[2*j], bl[2*j+1]);
                        MMA_BF16(acc[mt][np*2+j], al[mt], bh[2*j], bh[2*j+1]);
                    }
                }
            }
        }
        __syncthreads();
    }

    // ---- epilogue ----
    int rg = warp_m*64 + (lane >> 2);
    int cg = warp_n*64 + (lane & 3) * 2;

    if (which < 2) {
        __half* Dst = (which == 0) ? g_Qf : g_Kf;
        #pragma unroll
        for (int mt = 0; mt < 4; ++mt) {
            #pragma unroll
            for (int nt = 0; nt < 8; ++nt) {
                int r = rg + mt*16, c = cg + nt*8;
                float b0 = bias[c], b1 = bias[c+1];
                #pragma unroll
                for (int hv = 0; hv < 2; ++hv) {
                    int rr = r + hv*8;
                    float v0 = acc[mt][nt][hv*2]   + b0;
                    float v1 = acc[mt][nt][hv*2+1] + b1;
                    *(u32*)&Dst[(size_t)(m0 + rr) * Cn + c] = h2u(v0, v1);
                }
            }
        }
    } else {
        // V: stage fp16 transposed [e][s] then coalesced write to g_Vt
        __half* stage = (__half*)alig;       // [256 e][136 pad]
        #pragma unroll
        for (int mt = 0; mt < 4; ++mt) {
            #pragma unroll
            for (int nt = 0; nt < 8; ++nt) {
                int r = rg + mt*16, c = cg + nt*8;
                float b0 = bias[c], b1 = bias[c+1];
                #pragma unroll
                for (int hv = 0; hv < 2; ++hv) {
                    int rr = r + hv*8;
                    stage[(c)   * 136 + rr] = __float2half_rn(acc[mt][nt][hv*2]   + b0);
                    stage[(c+1) * 136 + rr] = __float2half_rn(acc[mt][nt][hv*2+1] + b1);
                }
            }
        }
        __syncthreads();
        int b = m0 >> 12, s0 = m0 & 4095;
        #pragma unroll
        for (int i = t; i < 256 * 32; i += 256) {
            int e = i >> 5, sseg = i & 31;
            uint2 v;
            v.x = *(u32*)&stage[e*136 + sseg*4];
            v.y = *(u32*)&stage[e*136 + sseg*4 + 2];
            *(uint2*)&g_Vt[((size_t)(b * En + e)) * Sn + s0 + sseg*4] = v;
        }
    }
}

// ==================================================================
// Kernel 3: fused flash attention + sigmoid.
// Q fp16 (64KB resident), K fp16 double-buffered (2x32KB),
// V fp16 triple-buffered (3x32KB). 1-term QK, 1-term PV.
// smem 224KB, 2 syncs/tile, prefetch distance 2.
// ==================================================================
#define FK_Q  0
#define FK_K0 (64*1024)
#define FK_V0 (128*1024)
#define SMEM_FK (224*1024 + 1024)

__device__ __forceinline__ void load_k_tile(u32 base, int kb,
    const __half* Kf, int s0, int t)
{
    #pragma unroll
    for (int j = 0; j < 8; ++j) {
        int idx = t + 256*j;
        int cc = idx >> 9, rr = (idx >> 3) & 63, g = idx & 7;
        cp16(base + FK_K0 + kb*32768 + cc*8192 + SW128(rr*128 + g*16),
             Kf + (size_t)(s0 + rr)*Cn + cc*64 + g*8);
    }
    CP_COMMIT();
}

__device__ __forceinline__ void load_v_tile(u32 base, int vb,
    const __half* Vt, int s0, int t)
{
    #pragma unroll
    for (int j = 0; j < 8; ++j) {
        int idx = t + 256*j;
        int rr = idx >> 3, g = idx & 7;
        cp16(base + FK_V0 + vb*32768 + SW128(rr*128 + g*16),
             Vt + (size_t)rr*Sn + s0 + g*8);
    }
    CP_COMMIT();
}

__global__ __launch_bounds__(256, 1)
void flash_kernel(float* __restrict__ out)
{
    extern __shared__ __align__(1024) char dsm[];
    u32 sb0 = smem_u32(dsm);
    u32 base = (sb0 + 1023) & ~1023u;
    int t = threadIdx.x, wid = t >> 5, lane = t & 31;
    int b = blockIdx.y, m0 = blockIdx.x * 128;

    const __half* Qf = g_Qf + ((size_t)(b*Sn + m0))*Cn;
    const __half* Kf = g_Kf + (size_t)b*Sn*Cn;
    const __half* Vt = g_Vt + (size_t)b*En*Sn;

    // prologue: Q, K0, V0, K1, V1 (5 groups)
    #pragma unroll
    for (int j = 0; j < 16; ++j) {
        int idx = t + 256*j;
        int cc = idx >> 10, rr = (idx >> 3) & 127, g = idx & 7;
        cp16(base + FK_Q + cc*16384 + SW128(rr*128 + g*16),
             Qf + (size_t)rr*Cn + cc*64 + g*8);
    }
    CP_COMMIT();
    load_k_tile(base, 0, Kf, 0, t);
    load_v_tile(base, 0, Vt, 0, t);
    load_k_tile(base, 1, Kf, 64, t);
    load_v_tile(base, 1, Vt, 64, t);

    float o[32][4];
    #pragma unroll
    for (int i = 0; i < 32; ++i)
        #pragma unroll
        for (int j = 0; j < 4; ++j) o[i][j] = 0.f;
    float m0r = -INFINITY, m1r = -INFINITY, l0r = 0.f, l1r = 0.f;

    int a_row = wid*16 + (lane & 15);
    int a_ck  = (lane >> 4) & 1;
    int b_row = (lane & 7) + ((lane >> 4) << 3);
    int b_ck  = (lane >> 3) & 1;

    for (int kt = 0; kt < 64; ++kt) {
        // K(kt), V(kt) ready; pending = {K(kt+1), V(kt+1)} except last tile
        if (kt < 63) { CP_WAIT(2); } else { CP_WAIT(0); }
        __syncthreads();

        // ---- QK: 1-term fp16 ----
        u32 kbase = base + FK_K0 + (kt & 1)*32768;
        float s[8][4];
        #pragma unroll
        for (int i = 0; i < 8; ++i)
            #pragma unroll
            for (int j = 0; j < 4; ++j) s[i][j] = 0.f;

        #pragma unroll
        for (int ks = 0; ks < 16; ++ks) {
            int cc = ks >> 2, kl2 = ks & 3;
            u32 swA = SW128((u32)(a_row*128 + (2*kl2 + a_ck)*16));
            u32 aq[4];
            LDSM_X4(aq[0], aq[1], aq[2], aq[3], base + FK_Q + cc*16384 + swA);
            #pragma unroll
            for (int ng = 0; ng < 4; ++ng) {
                u32 swB = SW128((u32)((b_row + ng*16)*128 + (2*kl2 + b_ck)*16));
                u32 bh[4];
                LDSM_X4(bh[0], bh[1], bh[2], bh[3], kbase + cc*8192 + swB);
                MMA_F16(s[ng*2],   aq, bh[0], bh[1]);
                MMA_F16(s[ng*2+1], aq, bh[2], bh[3]);
            }
        }
        __syncthreads();                   // all warps done reading K(kt)

        // prefetch tile kt+2 (K overwrites K(kt); V overwrites V(kt-1))
        if (kt + 2 < 64) {
            load_k_tile(base, (kt+2)&1, Kf, (kt+2)*64, t);
            load_v_tile(base, (kt+2)%3, Vt, (kt+2)*64, t);
        }

        // ---- online softmax on 2 owned rows ----
        float mx0 = s[0][0], mx1 = s[0][2];
        #pragma unroll
        for (int nt = 0; nt < 8; ++nt) {
            mx0 = fmaxf(mx0, fmaxf(s[nt][0], s[nt][1]));
            mx1 = fmaxf(mx1, fmaxf(s[nt][2], s[nt][3]));
        }
        mx0 = fmaxf(mx0, __shfl_xor_sync(0xffffffffu, mx0, 1));
        mx0 = fmaxf(mx0, __shfl_xor_sync(0xffffffffu, mx0, 2));
        mx1 = fmaxf(mx1, __shfl_xor_sync(0xffffffffu, mx1, 1));
        mx1 = fmaxf(mx1, __shfl_xor_sync(0xffffffffu, mx1, 2));
        float mn0 = fmaxf(m0r, mx0), mn1 = fmaxf(m1r, mx1);
        float sc0 = __expf(m0r - mn0), sc1 = __expf(m1r - mn1);
        m0r = mn0; m1r = mn1;

        float sum0 = 0.f, sum1 = 0.f;
        #pragma unroll
        for (int nt = 0; nt < 8; ++nt) {
            s[nt][0] = __expf(s[nt][0] - mn0);
            s[nt][1] = __expf(s[nt][1] - mn0);
            s[nt][2] = __expf(s[nt][2] - mn1);
            s[nt][3] = __expf(s[nt][3] - mn1);
            sum0 += s[nt][0] + s[nt][1];
            sum1 += s[nt][2] + s[nt][3];
        }
        sum0 += __shfl_xor_sync(0xffffffffu, sum0, 1);
        sum0 += __shfl_xor_sync(0xffffffffu, sum0, 2);
        sum1 += __shfl_xor_sync(0xffffffffu, sum1, 1);
        sum1 += __shfl_xor_sync(0xffffffffu, sum1, 2);
        l0r = l0r * sc0 + sum0;
        l1r = l1r * sc1 + sum1;

        if (!__all_sync(0xffffffffu, (sc0 == 1.f) & (sc1 == 1.f))) {
            #pragma unroll
            for (int nb = 0; nb < 32; ++nb) {
                o[nb][0] *= sc0; o[nb][1] *= sc0;
                o[nb][2] *= sc1; o[nb][3] *= sc1;
            }
        }

        // ---- pack P (C-frag -> A-frag, fp16) ----
        u32 af[4][4];
        #pragma unroll
        for (int ka = 0; ka < 4; ++ka) {
            af[ka][0] = h2u(s[2*ka][0],   s[2*ka][1]);
            af[ka][1] = h2u(s[2*ka][2],   s[2*ka][3]);
            af[ka][2] = h2u(s[2*ka+1][0], s[2*ka+1][1]);
            af[ka][3] = h2u(s[2*ka+1][2], s[2*ka+1][3]);
        }

        // ---- PV (V(kt) already waited at tile top) ----
        u32 vbase = base + FK_V0 + (kt % 3)*32768;
        #pragma unroll
        for (int ka = 0; ka < 4; ++ka) {
            #pragma unroll
            for (int nb = 0; nb < 16; ++nb) {
                u32 swV = SW128((u32)((b_row + nb*16)*128 + (2*ka + b_ck)*16));
                u32 bf[4];
                LDSM_X4(bf[0], bf[1], bf[2], bf[3], vbase + swV);
                MMA_F16(o[nb*2],   af[ka], bf[0], bf[1]);
                MMA_F16(o[nb*2+1], af[ka], bf[2], bf[3]);
            }
        }
        // no trailing sync: V buffer reuse distance is 3; K overwrite fenced
        // by next tile-top barrier pair.
    }

    // ---- epilogue: normalize, sigmoid, store ----
    float i0 = 1.f / l0r, i1 = 1.f / l1r;
    int row0 = m0 + wid*16 + (lane >> 2);
    float* O0 = out + ((size_t)b*Sn + row0) * En;
    #pragma unroll
    for (int nb = 0; nb < 32; ++nb) {
        int c = nb*8 + (lane & 3)*2;
        float2 v0, v1;
        v0.x = 1.f / (1.f + __expf(-o[nb][0] * i0));
        v0.y = 1.f / (1.f + __expf(-o[nb][1] * i0));
        v1.x = 1.f / (1.f + __expf(-o[nb][2] * i1));
        v1.y = 1.f / (1.f + __expf(-o[nb][3] * i1));
        *(float2*)&O0[c]          = v0;
        *(float2*)&O0[8*En + c]   = v1;
    }
}

// ==================================================================
// Launch
// ==================================================================
extern "C" void kernel_launch(void* const* d_in, const int* in_sizes, int n_in,
                              void* d_out, int out_size)
{
    const float* x  = (const float*)d_in[0];
    const float* Wq = (const float*)d_in[1];
    const float* bq = (const float*)d_in[2];
    const float* Wk = (const float*)d_in[3];
    const float* bk = (const float*)d_in[4];
    const float* Wv = (const float*)d_in[5];
    const float* bv = (const float*)d_in[6];
    float* out = (float*)d_out;

    cudaFuncSetAttribute(qkv_mma_kernel,
        cudaFuncAttributeMaxDynamicSharedMemorySize, SMEM_GEMM);
    cudaFuncSetAttribute(flash_kernel,
        cudaFuncAttributeMaxDynamicSharedMemorySize, SMEM_FK);

    split_x_kernel<<<Mtot * Cn / 1024, 256>>>(x);
    prep_w_kernel<<<dim3(8, 8, 3), dim3(32, 8)>>>(Wq, Wk, Wv);
    qkv_mma_kernel<<<dim3(128, 3), 256, SMEM_GEMM>>>(bq, bk, bv);
    flash_kernel<<<dim3(32, 4), 256, SMEM_FK>>>(out);
}